// round 11
// baseline (speedup 1.0000x reference)
#include <cuda_runtime.h>
#include <cuda_bf16.h>
#include <cstdint>

// ---------------- scratch (static __device__, no allocation) ----------------
#define MAXB 32
#define MAXN 500000
#define CAP  4096

__device__ float        g_pool8 [MAXB * 8 * 512];
__device__ float        g_query [MAXB * 512];            // [query b][K-dim]
__device__ float        g_scores[(size_t)MAXB * MAXN];   // 64 MB (coarse tf32 scores)
__device__ unsigned int g_rowmax[MAXB];
__device__ int          g_ccount[MAXB];
__device__ int          g_cidx  [MAXB * CAP];

__device__ __forceinline__ unsigned int fmono(float f) {
    unsigned int u = __float_as_uint(f);
    return (u & 0x80000000u) ? ~u : (u | 0x80000000u);
}

__device__ __forceinline__ void cp_async16(void* smem_dst, const void* gmem_src) {
    unsigned int d = (unsigned int)__cvta_generic_to_shared(smem_dst);
    asm volatile("cp.async.cg.shared.global [%0], [%1], 16;" :: "r"(d), "l"(gmem_src));
}

// tf32 warp MMA: D(16x8) += A(16x8) * B(8x8); A row-major, B col-major.
__device__ __forceinline__ void mma_tf32(float d[4], const unsigned int a[4],
                                         const unsigned int b[2]) {
    asm volatile(
        "mma.sync.aligned.m16n8k8.row.col.f32.tf32.tf32.f32 "
        "{%0,%1,%2,%3}, {%4,%5,%6,%7}, {%8,%9}, {%0,%1,%2,%3};"
        : "+f"(d[0]), "+f"(d[1]), "+f"(d[2]), "+f"(d[3])
        : "r"(a[0]), "r"(a[1]), "r"(a[2]), "r"(a[3]), "r"(b[0]), "r"(b[1]));
}

#define INV_SQRT_D 0.04419417382415922f   // 1/sqrt(512)
#define MARGIN_BINS 5       // collect threshold: rowmax bin - 5 (value factor ~1.54)
#define WINDOW_BINS 15      // fallback window floor (2 octaves below max)

// ---------------- K0: zero small scratch ----------------
__global__ void k_zero() {
    int i = threadIdx.x;
    if (i < MAXB) { g_ccount[i] = 0; g_rowmax[i] = 0u; }
}

// ---------------- K1: partial mean over T chunks ----------------
__global__ void k_mean(const float* __restrict__ hidden, int T) {
    int b  = blockIdx.x;
    int tc = blockIdx.y;              // 8 chunks
    int d  = threadIdx.x;             // 512 threads
    int rows_per = (T + 7) / 8;
    int t0 = tc * rows_per;
    int t1 = t0 + rows_per; if (t1 > T) t1 = T;
    const float* hp = hidden + ((size_t)b * T + t0) * 512 + d;
    float s0 = 0.f, s1 = 0.f, s2 = 0.f, s3 = 0.f;
    int nt = t1 - t0, t = 0;
    for (; t + 4 <= nt; t += 4) {
        s0 += hp[(size_t)(t + 0) * 512]; s1 += hp[(size_t)(t + 1) * 512];
        s2 += hp[(size_t)(t + 2) * 512]; s3 += hp[(size_t)(t + 3) * 512];
    }
    float s = (s0 + s1) + (s2 + s3);
    for (; t < nt; t++) s += hp[(size_t)t * 512];
    g_pool8[((size_t)b * 8 + tc) * 512 + d] = s;
}

// ---------------- K2: query[b][d] = (mean @ W + bias)[d] ----------------
__global__ void k_query(const float* __restrict__ W, const float* __restrict__ bias, int T) {
    __shared__ float p[512];
    int b = blockIdx.x, tid = threadIdx.x;          // 256 threads
    float invT = 1.0f / (float)T;
    for (int i = tid; i < 512; i += 256) {
        float s = 0.f;
#pragma unroll
        for (int tc = 0; tc < 8; tc++) s += g_pool8[((size_t)b * 8 + tc) * 512 + i];
        p[i] = s * invT;
    }
    __syncthreads();
    int d = tid * 2;
    float a0 = 0.f, a1 = 0.f;
#pragma unroll 16
    for (int k = 0; k < 512; k++) {
        float2 wv = *reinterpret_cast<const float2*>(W + (size_t)k * 512 + d);
        float pv = p[k];
        a0 += pv * wv.x; a1 += pv * wv.y;
    }
    g_query[(size_t)b * 512 + d]     = a0 + bias[d];
    g_query[(size_t)b * 512 + d + 1] = a1 + bias[d + 1];
}

// ---------------- K3: scores GEMM via mma.sync tf32 (measured 182us, 74% DRAM) ----------------
#define KSTR 20
__global__ void __launch_bounds__(128) k_scores(const float* __restrict__ keys, int N) {
    __shared__ float skey[2][256 * KSTR];   // 40960 B
    __shared__ float sqry[2][32 * KSTR];    //  5120 B
    __shared__ unsigned int s_max[32];
    int tid = threadIdx.x, lane = tid & 31, w = tid >> 5;
    int g = lane >> 2, tg = lane & 3;
    int n0 = blockIdx.x * 256;
    if (tid < 32) s_max[tid] = 0u;

    float d[2][8][4];
#pragma unroll
    for (int mt = 0; mt < 2; mt++)
#pragma unroll
        for (int nt = 0; nt < 8; nt++)
#pragma unroll
            for (int r = 0; r < 4; r++) d[mt][nt][r] = 0.f;

#define LOAD_CHUNK(CH, BUF)                                                       \
    do {                                                                          \
        int c0_ = (CH) * 16;                                                      \
        _Pragma("unroll")                                                         \
        for (int it = 0; it < 8; it++) {                                          \
            int v = it * 128 + tid;                                               \
            int row = v >> 2, g16 = v & 3;                                        \
            int n = n0 + row; if (n >= N) n = N - 1;                              \
            cp_async16(&skey[BUF][row * KSTR + g16 * 4],                          \
                       keys + (size_t)n * 512 + c0_ + g16 * 4);                   \
        }                                                                         \
        {                                                                         \
            int row = tid >> 2, g16 = tid & 3;                                    \
            cp_async16(&sqry[BUF][row * KSTR + g16 * 4],                          \
                       g_query + (size_t)row * 512 + c0_ + g16 * 4);              \
        }                                                                         \
        asm volatile("cp.async.commit_group;" ::: "memory");                      \
    } while (0)

    LOAD_CHUNK(0, 0);
    for (int ch = 0; ch < 32; ch++) {
        int buf = ch & 1;
        if (ch + 1 < 32) {
            LOAD_CHUNK(ch + 1, (ch + 1) & 1);
            asm volatile("cp.async.wait_group 1;" ::: "memory");
        } else {
            asm volatile("cp.async.wait_group 0;" ::: "memory");
        }
        __syncthreads();

#pragma unroll
        for (int ks = 0; ks < 2; ks++) {
            unsigned int a[2][4];
#pragma unroll
            for (int mt = 0; mt < 2; mt++) {
                int qr = mt * 16 + g;
                a[mt][0] = __float_as_uint(sqry[buf][qr * KSTR + ks * 8 + tg]);
                a[mt][1] = __float_as_uint(sqry[buf][(qr + 8) * KSTR + ks * 8 + tg]);
                a[mt][2] = __float_as_uint(sqry[buf][qr * KSTR + ks * 8 + tg + 4]);
                a[mt][3] = __float_as_uint(sqry[buf][(qr + 8) * KSTR + ks * 8 + tg + 4]);
            }
#pragma unroll
            for (int nt = 0; nt < 8; nt++) {
                int kr = w * 64 + nt * 8 + g;
                unsigned int b[2];
                b[0] = __float_as_uint(skey[buf][kr * KSTR + ks * 8 + tg]);
                b[1] = __float_as_uint(skey[buf][kr * KSTR + ks * 8 + tg + 4]);
                mma_tf32(d[0][nt], a[0], b);
                mma_tf32(d[1][nt], a[1], b);
            }
        }
        __syncthreads();
    }

#pragma unroll
    for (int mt = 0; mt < 2; mt++) {
        unsigned int m0 = 0u, m1 = 0u;
        int q0 = mt * 16 + g, q1 = q0 + 8;
#pragma unroll
        for (int nt = 0; nt < 8; nt++) {
            int key = n0 + w * 64 + nt * 8 + tg * 2;
            float v0 = d[mt][nt][0] * INV_SQRT_D;
            float v1 = d[mt][nt][1] * INV_SQRT_D;
            float v2 = d[mt][nt][2] * INV_SQRT_D;
            float v3 = d[mt][nt][3] * INV_SQRT_D;
            if (key + 1 < N) {
                *reinterpret_cast<float2*>(g_scores + (size_t)q0 * N + key) = make_float2(v0, v1);
                *reinterpret_cast<float2*>(g_scores + (size_t)q1 * N + key) = make_float2(v2, v3);
                unsigned int u;
                u = fmono(v0); if (u > m0) m0 = u;
                u = fmono(v1); if (u > m0) m0 = u;
                u = fmono(v2); if (u > m1) m1 = u;
                u = fmono(v3); if (u > m1) m1 = u;
            } else if (key < N) {
                g_scores[(size_t)q0 * N + key] = v0;
                g_scores[(size_t)q1 * N + key] = v2;
                unsigned int u;
                u = fmono(v0); if (u > m0) m0 = u;
                u = fmono(v2); if (u > m1) m1 = u;
            }
        }
        atomicMax(&s_max[q0], m0);
        atomicMax(&s_max[q1], m1);
    }
    __syncthreads();
    if (tid < 32 && s_max[tid]) atomicMax(&g_rowmax[tid], s_max[tid]);
}

// ---------------- K4: collect candidates with bin >= rowmax_bin - MARGIN_BINS ----------------
#define F4PB 8192   // float4s per block
__global__ void k_collect(int N) {
    int row = blockIdx.y;
    int N4  = N >> 2;
    unsigned int tb = (g_rowmax[row] >> 20) - MARGIN_BINS;
    const float4* sr = reinterpret_cast<const float4*>(g_scores + (size_t)row * N);
    int base = blockIdx.x * F4PB;
    for (int i = threadIdx.x; i < F4PB; i += 256) {
        int i4 = base + i;
        if (i4 < N4) {
            float4 v = sr[i4];
            unsigned int u[4] = {fmono(v.x), fmono(v.y), fmono(v.z), fmono(v.w)};
#pragma unroll
            for (int e = 0; e < 4; e++) {
                if ((u[e] >> 20) >= tb) {
                    int pos = atomicAdd(&g_ccount[row], 1);
                    if (pos < CAP) g_cidx[row * CAP + pos] = i4 * 4 + e;
                }
            }
        }
    }
    if (blockIdx.x == 0) {
        for (int idx = N4 * 4 + (int)threadIdx.x; idx < N; idx += 256) {
            unsigned int u = fmono(g_scores[(size_t)row * N + idx]);
            if ((u >> 20) >= tb) {
                int pos = atomicAdd(&g_ccount[row], 1);
                if (pos < CAP) g_cidx[row * CAP + pos] = idx;
            }
        }
    }
}

// ---------------- K5: fallback — if a row has < max_k candidates, widen window ----------------
__global__ void k_fallback(const int* __restrict__ pmk, int N) {
    int row = blockIdx.x;
    int mk = *pmk; if (mk < 1) mk = 1; if (mk > CAP) mk = CAP;
    if (g_ccount[row] >= mk) return;          // common case: one load, exit
    unsigned int hi = (g_rowmax[row] >> 20) - MARGIN_BINS;   // already collected >= hi
    unsigned int lo = (g_rowmax[row] >> 20) - WINDOW_BINS;
    const float* sr = g_scores + (size_t)row * N;
    for (int idx = threadIdx.x; idx < N; idx += 256) {
        unsigned int b = fmono(sr[idx]) >> 20;
        if (b >= lo && b < hi) {              // strictly below first threshold: no dups
            int pos = atomicAdd(&g_ccount[row], 1);
            if (pos < CAP) g_cidx[row * CAP + pos] = idx;
        }
    }
}

// ---------------- K6: EXACT fp32 rescore, rank, softmax(k_dyn), gather ----------------
__global__ void k_final(const float* __restrict__ pool_params, const float* __restrict__ keys,
                        const int* __restrict__ pkd, float* __restrict__ out, int N) {
    __shared__ int   ci[CAP];
    __shared__ float se[CAP];
    __shared__ float q[512];
    __shared__ float selS[64];
    __shared__ int   selI[64];
    __shared__ float w[64];
    int row = blockIdx.x;
    int c   = g_ccount[row]; if (c > CAP) c = CAP;
    for (int i = threadIdx.x; i < c; i += 256) ci[i] = g_cidx[row * CAP + i];
    for (int i = threadIdx.x; i < 512; i += 256) q[i] = g_query[(size_t)row * 512 + i];
    __syncthreads();

    // exact rescore: one warp per candidate
    int lane = threadIdx.x & 31, wrp = threadIdx.x >> 5;
    for (int cand = wrp; cand < c; cand += 8) {
        const float* kr = keys + (size_t)ci[cand] * 512;
        float s = 0.f;
#pragma unroll 4
        for (int k = lane; k < 512; k += 32) s += kr[k] * q[k];
#pragma unroll
        for (int o = 16; o; o >>= 1) s += __shfl_xor_sync(0xffffffffu, s, o);
        if (lane == 0) se[cand] = s * INV_SQRT_D;
    }
    __syncthreads();

    // exact rank on exact scores: (score desc, index asc) = jax.lax.top_k order
    for (int i = threadIdx.x; i < c; i += 256) {
        float si = se[i]; int idi = ci[i];
        int r = 0;
        for (int j = 0; j < c; j++) {
            float sj = se[j];
            r += (sj > si) || (sj == si && ci[j] < idi);
        }
        if (r < 64) { selS[r] = si; selI[r] = idi; }
    }
    __syncthreads();
    int kd = *pkd; if (kd > 64) kd = 64; if (kd < 1) kd = 1;
    if (kd > c) kd = c;
    if (threadIdx.x == 0) {
        float mx = selS[0];
        float sum = 0.f;
        for (int r = 0; r < kd; r++) { float e = expf(selS[r] - mx); w[r] = e; sum += e; }
        float inv = 1.0f / sum;
        for (int r = 0; r < kd; r++) w[r] *= inv;
    }
    __syncthreads();
    for (int d = threadIdx.x; d < 512; d += 256) {
        float acc = 0.f;
        for (int r = 0; r < kd; r++)
            acc += w[r] * pool_params[(size_t)selI[r] * 512 + d];
        out[row * 512 + d] = acc;
    }
}

// ---------------- launch ----------------
extern "C" void kernel_launch(void* const* d_in, const int* in_sizes, int n_in,
                              void* d_out, int out_size) {
    const float* hidden      = (const float*)d_in[0];
    const float* pool_params = (const float*)d_in[1];
    const float* pool_keys   = (const float*)d_in[2];
    const float* W           = (const float*)d_in[3];
    const float* bias        = (const float*)d_in[4];
    const int*   pkd         = (const int*)d_in[5];
    const int*   pmk         = (const int*)d_in[6];

    int B = out_size / 512;          if (B > MAXB) B = MAXB;
    int T = in_sizes[0] / (B * 512);
    int N = in_sizes[2] / 512;       if (N > MAXN) N = MAXN;

    k_zero<<<1, 32>>>();
    k_mean<<<dim3(B, 8), 512>>>(hidden, T);
    k_query<<<B, 256>>>(W, bias, T);
    k_scores<<<(N + 255) / 256, 128>>>(pool_keys, N);
    int gx = ((N >> 2) + F4PB - 1) / F4PB;
    k_collect<<<dim3(gx, B), 256>>>(N);
    k_fallback<<<B, 256>>>(pmk, N);
    k_final<<<B, 256>>>(pool_params, pool_keys, pkd, (float*)d_out, N);
}

// round 12
// speedup vs baseline: 3.5626x; 3.5626x over previous
#include <cuda_runtime.h>
#include <cuda_bf16.h>
#include <cstdint>

// ---------------- scratch (static __device__, no allocation) ----------------
#define MAXB 32
#define MAXN 500000
#define CAP  4096
#define SEL  96      // coarse top-SEL get exact fp32 rescore (64 + 32 slack)

__device__ float        g_pool8 [MAXB * 8 * 512];
__device__ float        g_query [MAXB * 512];            // [query b][K-dim]
__device__ float        g_scores[(size_t)MAXB * MAXN];   // 64 MB (coarse tf32 scores)
__device__ unsigned int g_rowmax[MAXB];
__device__ unsigned int g_hist16[MAXB * 16];
__device__ unsigned int g_thresh[MAXB];
__device__ int          g_ccount[MAXB];
__device__ unsigned int g_cu    [MAXB * CAP];
__device__ int          g_cidx  [MAXB * CAP];

__device__ __forceinline__ unsigned int fmono(float f) {
    unsigned int u = __float_as_uint(f);
    return (u & 0x80000000u) ? ~u : (u | 0x80000000u);
}

__device__ __forceinline__ void cp_async16(void* smem_dst, const void* gmem_src) {
    unsigned int d = (unsigned int)__cvta_generic_to_shared(smem_dst);
    asm volatile("cp.async.cg.shared.global [%0], [%1], 16;" :: "r"(d), "l"(gmem_src));
}

// tf32 warp MMA: D(16x8) += A(16x8) * B(8x8); A row-major, B col-major.
__device__ __forceinline__ void mma_tf32(float d[4], const unsigned int a[4],
                                         const unsigned int b[2]) {
    asm volatile(
        "mma.sync.aligned.m16n8k8.row.col.f32.tf32.tf32.f32 "
        "{%0,%1,%2,%3}, {%4,%5,%6,%7}, {%8,%9}, {%0,%1,%2,%3};"
        : "+f"(d[0]), "+f"(d[1]), "+f"(d[2]), "+f"(d[3])
        : "r"(a[0]), "r"(a[1]), "r"(a[2]), "r"(a[3]), "r"(b[0]), "r"(b[1]));
}

#define INV_SQRT_D 0.04419417382415922f   // 1/sqrt(512)

// ---------------- K0: zero small scratch ----------------
__global__ void k_zero() {
    int i = threadIdx.x;
    if (i < MAXB * 16) g_hist16[i] = 0u;
    if (i < MAXB) { g_ccount[i] = 0; g_rowmax[i] = 0u; }
}

// ---------------- K1: partial mean over T chunks ----------------
__global__ void k_mean(const float* __restrict__ hidden, int T) {
    int b  = blockIdx.x;
    int tc = blockIdx.y;              // 8 chunks
    int d  = threadIdx.x;             // 512 threads
    int rows_per = (T + 7) / 8;
    int t0 = tc * rows_per;
    int t1 = t0 + rows_per; if (t1 > T) t1 = T;
    const float* hp = hidden + ((size_t)b * T + t0) * 512 + d;
    float s0 = 0.f, s1 = 0.f, s2 = 0.f, s3 = 0.f;
    int nt = t1 - t0, t = 0;
    for (; t + 4 <= nt; t += 4) {
        s0 += hp[(size_t)(t + 0) * 512]; s1 += hp[(size_t)(t + 1) * 512];
        s2 += hp[(size_t)(t + 2) * 512]; s3 += hp[(size_t)(t + 3) * 512];
    }
    float s = (s0 + s1) + (s2 + s3);
    for (; t < nt; t++) s += hp[(size_t)t * 512];
    g_pool8[((size_t)b * 8 + tc) * 512 + d] = s;
}

// ---------------- K2: query[b][d] = (mean @ W + bias)[d] ----------------
__global__ void k_query(const float* __restrict__ W, const float* __restrict__ bias, int T) {
    __shared__ float p[512];
    int b = blockIdx.x, tid = threadIdx.x;          // 256 threads
    float invT = 1.0f / (float)T;
    for (int i = tid; i < 512; i += 256) {
        float s = 0.f;
#pragma unroll
        for (int tc = 0; tc < 8; tc++) s += g_pool8[((size_t)b * 8 + tc) * 512 + i];
        p[i] = s * invT;
    }
    __syncthreads();
    int d = tid * 2;
    float a0 = 0.f, a1 = 0.f;
#pragma unroll 16
    for (int k = 0; k < 512; k++) {
        float2 wv = *reinterpret_cast<const float2*>(W + (size_t)k * 512 + d);
        float pv = p[k];
        a0 += pv * wv.x; a1 += pv * wv.y;
    }
    g_query[(size_t)b * 512 + d]     = a0 + bias[d];
    g_query[(size_t)b * 512 + d + 1] = a1 + bias[d + 1];
}

// ---------------- K3: scores GEMM via mma.sync tf32 (measured 182us isolated) ----------------
#define KSTR 20
__global__ void __launch_bounds__(128) k_scores(const float* __restrict__ keys, int N) {
    __shared__ float skey[2][256 * KSTR];   // 40960 B
    __shared__ float sqry[2][32 * KSTR];    //  5120 B
    __shared__ unsigned int s_max[32];
    int tid = threadIdx.x, lane = tid & 31, w = tid >> 5;
    int g = lane >> 2, tg = lane & 3;
    int n0 = blockIdx.x * 256;
    if (tid < 32) s_max[tid] = 0u;

    float d[2][8][4];
#pragma unroll
    for (int mt = 0; mt < 2; mt++)
#pragma unroll
        for (int nt = 0; nt < 8; nt++)
#pragma unroll
            for (int r = 0; r < 4; r++) d[mt][nt][r] = 0.f;

#define LOAD_CHUNK(CH, BUF)                                                       \
    do {                                                                          \
        int c0_ = (CH) * 16;                                                      \
        _Pragma("unroll")                                                         \
        for (int it = 0; it < 8; it++) {                                          \
            int v = it * 128 + tid;                                               \
            int row = v >> 2, g16 = v & 3;                                        \
            int n = n0 + row; if (n >= N) n = N - 1;                              \
            cp_async16(&skey[BUF][row * KSTR + g16 * 4],                          \
                       keys + (size_t)n * 512 + c0_ + g16 * 4);                   \
        }                                                                         \
        {                                                                         \
            int row = tid >> 2, g16 = tid & 3;                                    \
            cp_async16(&sqry[BUF][row * KSTR + g16 * 4],                          \
                       g_query + (size_t)row * 512 + c0_ + g16 * 4);              \
        }                                                                         \
        asm volatile("cp.async.commit_group;" ::: "memory");                      \
    } while (0)

    LOAD_CHUNK(0, 0);
    for (int ch = 0; ch < 32; ch++) {
        int buf = ch & 1;
        if (ch + 1 < 32) {
            LOAD_CHUNK(ch + 1, (ch + 1) & 1);
            asm volatile("cp.async.wait_group 1;" ::: "memory");
        } else {
            asm volatile("cp.async.wait_group 0;" ::: "memory");
        }
        __syncthreads();

#pragma unroll
        for (int ks = 0; ks < 2; ks++) {
            unsigned int a[2][4];
#pragma unroll
            for (int mt = 0; mt < 2; mt++) {
                int qr = mt * 16 + g;
                a[mt][0] = __float_as_uint(sqry[buf][qr * KSTR + ks * 8 + tg]);
                a[mt][1] = __float_as_uint(sqry[buf][(qr + 8) * KSTR + ks * 8 + tg]);
                a[mt][2] = __float_as_uint(sqry[buf][qr * KSTR + ks * 8 + tg + 4]);
                a[mt][3] = __float_as_uint(sqry[buf][(qr + 8) * KSTR + ks * 8 + tg + 4]);
            }
#pragma unroll
            for (int nt = 0; nt < 8; nt++) {
                int kr = w * 64 + nt * 8 + g;
                unsigned int b[2];
                b[0] = __float_as_uint(skey[buf][kr * KSTR + ks * 8 + tg]);
                b[1] = __float_as_uint(skey[buf][kr * KSTR + ks * 8 + tg + 4]);
                mma_tf32(d[0][nt], a[0], b);
                mma_tf32(d[1][nt], a[1], b);
            }
        }
        __syncthreads();
    }

#pragma unroll
    for (int mt = 0; mt < 2; mt++) {
        unsigned int m0 = 0u, m1 = 0u;
        int q0 = mt * 16 + g, q1 = q0 + 8;
#pragma unroll
        for (int nt = 0; nt < 8; nt++) {
            int key = n0 + w * 64 + nt * 8 + tg * 2;
            float v0 = d[mt][nt][0] * INV_SQRT_D;
            float v1 = d[mt][nt][1] * INV_SQRT_D;
            float v2 = d[mt][nt][2] * INV_SQRT_D;
            float v3 = d[mt][nt][3] * INV_SQRT_D;
            if (key + 1 < N) {
                *reinterpret_cast<float2*>(g_scores + (size_t)q0 * N + key) = make_float2(v0, v1);
                *reinterpret_cast<float2*>(g_scores + (size_t)q1 * N + key) = make_float2(v2, v3);
                unsigned int u;
                u = fmono(v0); if (u > m0) m0 = u;
                u = fmono(v1); if (u > m0) m0 = u;
                u = fmono(v2); if (u > m1) m1 = u;
                u = fmono(v3); if (u > m1) m1 = u;
            } else if (key < N) {
                g_scores[(size_t)q0 * N + key] = v0;
                g_scores[(size_t)q1 * N + key] = v2;
                unsigned int u;
                u = fmono(v0); if (u > m0) m0 = u;
                u = fmono(v2); if (u > m1) m1 = u;
            }
        }
        atomicMax(&s_max[q0], m0);
        atomicMax(&s_max[q1], m1);
    }
    __syncthreads();
    if (tid < 32 && s_max[tid]) atomicMax(&g_rowmax[tid], s_max[tid]);
}

// ---------------- K4: 16-bin hist restricted to top bins below rowmax (R8-proven) ----------------
#define F4PB 8192   // float4s per block
__global__ void k_hist(int N) {
    __shared__ unsigned int h[16];
    int row = blockIdx.y;
    int N4  = N >> 2;
    if (threadIdx.x < 16) h[threadIdx.x] = 0u;
    __syncthreads();
    int lo = (int)(g_rowmax[row] >> 20) - 15;
    const float4* sr = reinterpret_cast<const float4*>(g_scores + (size_t)row * N);
    int base = blockIdx.x * F4PB;
    for (int i = threadIdx.x; i < F4PB; i += 256) {
        int i4 = base + i;
        if (i4 < N4) {
            float4 v = sr[i4];
            int b0 = (int)(fmono(v.x) >> 20) - lo;
            int b1 = (int)(fmono(v.y) >> 20) - lo;
            int b2 = (int)(fmono(v.z) >> 20) - lo;
            int b3 = (int)(fmono(v.w) >> 20) - lo;
            if (b0 >= 0) atomicAdd(&h[b0], 1u);
            if (b1 >= 0) atomicAdd(&h[b1], 1u);
            if (b2 >= 0) atomicAdd(&h[b2], 1u);
            if (b3 >= 0) atomicAdd(&h[b3], 1u);
        }
    }
    if (blockIdx.x == 0) {
        for (int idx = N4 * 4 + (int)threadIdx.x; idx < N; idx += 256) {
            int b = (int)(fmono(g_scores[(size_t)row * N + idx]) >> 20) - lo;
            if (b >= 0) atomicAdd(&h[b], 1u);
        }
    }
    __syncthreads();
    if (threadIdx.x < 16 && h[threadIdx.x])
        atomicAdd(&g_hist16[row * 16 + threadIdx.x], h[threadIdx.x]);
}

// ---------------- K5: threshold bin (cum from top >= max_k), one safety bin ----------------
__global__ void k_thresh(const int* __restrict__ pmk) {
    int row = blockIdx.x;
    if (threadIdx.x == 0) {
        int lo = (int)(g_rowmax[row] >> 20) - 15;
        int mk = *pmk; if (mk < 1) mk = 1; if (mk > CAP) mk = CAP;
        unsigned int cum = 0;
        int bfound = 0;
        for (int b = 15; b >= 0; b--) {
            cum += g_hist16[row * 16 + b];
            if (cum >= (unsigned int)mk) { bfound = b; break; }
        }
        int bsafe = bfound > 0 ? bfound - 1 : 0;   // one-bin margin for tf32 + bin edges
        g_thresh[row] = (unsigned int)(lo + bsafe);
    }
}

// ---------------- K6: collect candidates (coarse key + index) ----------------
__global__ void k_collect(int N) {
    int row = blockIdx.y;
    int N4  = N >> 2;
    unsigned int tb = g_thresh[row];
    const float4* sr = reinterpret_cast<const float4*>(g_scores + (size_t)row * N);
    int base = blockIdx.x * F4PB;
    for (int i = threadIdx.x; i < F4PB; i += 256) {
        int i4 = base + i;
        if (i4 < N4) {
            float4 v = sr[i4];
            unsigned int u[4] = {fmono(v.x), fmono(v.y), fmono(v.z), fmono(v.w)};
#pragma unroll
            for (int e = 0; e < 4; e++) {
                if ((u[e] >> 20) >= tb) {
                    int pos = atomicAdd(&g_ccount[row], 1);
                    if (pos < CAP) {
                        g_cu  [row * CAP + pos] = u[e];
                        g_cidx[row * CAP + pos] = i4 * 4 + e;
                    }
                }
            }
        }
    }
    if (blockIdx.x == 0) {
        for (int idx = N4 * 4 + (int)threadIdx.x; idx < N; idx += 256) {
            unsigned int u = fmono(g_scores[(size_t)row * N + idx]);
            if ((u >> 20) >= tb) {
                int pos = atomicAdd(&g_ccount[row], 1);
                if (pos < CAP) {
                    g_cu  [row * CAP + pos] = u;
                    g_cidx[row * CAP + pos] = idx;
                }
            }
        }
    }
}

// ---------------- K7: coarse top-SEL, exact rescore of SEL, exact rank, softmax, gather ----------------
__global__ void k_final(const float* __restrict__ pool_params, const float* __restrict__ keys,
                        const int* __restrict__ pkd, float* __restrict__ out, int N) {
    __shared__ unsigned int cu[CAP];
    __shared__ int          ci[CAP];
    __shared__ float        q[512];
    __shared__ int          sI[SEL];      // coarse top-SEL candidate indices
    __shared__ float        sE[SEL];      // exact scores of those
    __shared__ float        selS[64];
    __shared__ int          selI[64];
    __shared__ float        w[64];
    int row = blockIdx.x;
    int c   = g_ccount[row]; if (c > CAP) c = CAP;
    for (int i = threadIdx.x; i < c; i += 256) {
        cu[i] = g_cu  [row * CAP + i];
        ci[i] = g_cidx[row * CAP + i];
    }
    for (int i = threadIdx.x; i < 512; i += 256) q[i] = g_query[(size_t)row * 512 + i];
    __syncthreads();

    // coarse rank (R8-proven fast path): (coarse desc, index asc)
    int nsel = c < SEL ? c : SEL;
    for (int i = threadIdx.x; i < c; i += 256) {
        unsigned int ui = cu[i];
        int idi = ci[i];
        int r = 0;
        for (int j = 0; j < c; j++) {
            unsigned int uj = cu[j];
            r += (uj > ui) || (uj == ui && ci[j] < idi);
        }
        if (r < SEL) sI[r] = idi;
    }
    __syncthreads();

    // exact fp32 rescore of the coarse top-SEL: one warp per candidate
    int lane = threadIdx.x & 31, wrp = threadIdx.x >> 5;
    for (int cand = wrp; cand < nsel; cand += 8) {
        const float* kr = keys + (size_t)sI[cand] * 512;
        float s = 0.f;
#pragma unroll 4
        for (int k = lane; k < 512; k += 32) s += kr[k] * q[k];
#pragma unroll
        for (int o = 16; o; o >>= 1) s += __shfl_xor_sync(0xffffffffu, s, o);
        if (lane == 0) sE[cand] = s * INV_SQRT_D;
    }
    __syncthreads();

    // exact rank among nsel: (score desc, index asc) = jax.lax.top_k order
    if (threadIdx.x < (unsigned)nsel) {
        float si = sE[threadIdx.x]; int idi = sI[threadIdx.x];
        int r = 0;
        for (int j = 0; j < nsel; j++) {
            float sj = sE[j];
            r += (sj > si) || (sj == si && sI[j] < idi);
        }
        if (r < 64) { selS[r] = si; selI[r] = idi; }
    }
    __syncthreads();
    int kd = *pkd; if (kd > 64) kd = 64; if (kd < 1) kd = 1;
    if (kd > nsel) kd = nsel;
    if (threadIdx.x == 0) {
        float mx = selS[0];
        float sum = 0.f;
        for (int r = 0; r < kd; r++) { float e = expf(selS[r] - mx); w[r] = e; sum += e; }
        float inv = 1.0f / sum;
        for (int r = 0; r < kd; r++) w[r] *= inv;
    }
    __syncthreads();
    for (int d = threadIdx.x; d < 512; d += 256) {
        float acc = 0.f;
        for (int r = 0; r < kd; r++)
            acc += w[r] * pool_params[(size_t)selI[r] * 512 + d];
        out[row * 512 + d] = acc;
    }
}

// ---------------- launch ----------------
extern "C" void kernel_launch(void* const* d_in, const int* in_sizes, int n_in,
                              void* d_out, int out_size) {
    const float* hidden      = (const float*)d_in[0];
    const float* pool_params = (const float*)d_in[1];
    const float* pool_keys   = (const float*)d_in[2];
    const float* W           = (const float*)d_in[3];
    const float* bias        = (const float*)d_in[4];
    const int*   pkd         = (const int*)d_in[5];
    const int*   pmk         = (const int*)d_in[6];

    int B = out_size / 512;          if (B > MAXB) B = MAXB;
    int T = in_sizes[0] / (B * 512);
    int N = in_sizes[2] / 512;       if (N > MAXN) N = MAXN;

    k_zero<<<1, 1024>>>();
    k_mean<<<dim3(B, 8), 512>>>(hidden, T);
    k_query<<<B, 256>>>(W, bias, T);
    k_scores<<<(N + 255) / 256, 128>>>(pool_keys, N);
    int gx = ((N >> 2) + F4PB - 1) / F4PB;
    k_hist<<<dim3(gx, B), 256>>>(N);
    k_thresh<<<B, 32>>>(pmk);
    k_collect<<<dim3(gx, B), 256>>>(N);
    k_final<<<B, 256>>>(pool_params, pool_keys, pkd, (float*)d_out, N);
}

// round 13
// speedup vs baseline: 4.0988x; 1.1505x over previous
#include <cuda_runtime.h>
#include <cuda_bf16.h>
#include <cstdint>

// ---------------- scratch (static __device__, no allocation) ----------------
#define MAXB 32
#define MAXN 500000
#define CAP  4096
#define SEL  96      // coarse top-SEL get exact fp32 rescore (64 + 32 slack)
#define MAXNB 2048   // max score blocks per row (ceil(500000/256)=1954)

__device__ float        g_pool8 [MAXB * 8 * 512];
__device__ float        g_query [MAXB * 512];            // [query b][K-dim]
__device__ float        g_scores[(size_t)MAXB * MAXN];   // 64 MB (coarse tf32 scores)
__device__ unsigned int g_bmax  [MAXB * MAXNB];          // per-row per-block max (mono)
__device__ int          g_ccount[MAXB];
__device__ unsigned int g_cu    [MAXB * CAP];
__device__ int          g_cidx  [MAXB * CAP];

__device__ __forceinline__ unsigned int fmono(float f) {
    unsigned int u = __float_as_uint(f);
    return (u & 0x80000000u) ? ~u : (u | 0x80000000u);
}

__device__ __forceinline__ void cp_async16(void* smem_dst, const void* gmem_src) {
    unsigned int d = (unsigned int)__cvta_generic_to_shared(smem_dst);
    asm volatile("cp.async.cg.shared.global [%0], [%1], 16;" :: "r"(d), "l"(gmem_src));
}

// tf32 warp MMA: D(16x8) += A(16x8) * B(8x8); A row-major, B col-major.
__device__ __forceinline__ void mma_tf32(float d[4], const unsigned int a[4],
                                         const unsigned int b[2]) {
    asm volatile(
        "mma.sync.aligned.m16n8k8.row.col.f32.tf32.tf32.f32 "
        "{%0,%1,%2,%3}, {%4,%5,%6,%7}, {%8,%9}, {%0,%1,%2,%3};"
        : "+f"(d[0]), "+f"(d[1]), "+f"(d[2]), "+f"(d[3])
        : "r"(a[0]), "r"(a[1]), "r"(a[2]), "r"(a[3]), "r"(b[0]), "r"(b[1]));
}

#define INV_SQRT_D 0.04419417382415922f   // 1/sqrt(512)

// ---------------- K0: zero candidate counters ----------------
__global__ void k_zero() {
    if (threadIdx.x < MAXB) g_ccount[threadIdx.x] = 0;
}

// ---------------- K1: partial mean over T chunks ----------------
__global__ void k_mean(const float* __restrict__ hidden, int T) {
    int b  = blockIdx.x;
    int tc = blockIdx.y;              // 8 chunks
    int d  = threadIdx.x;             // 512 threads
    int rows_per = (T + 7) / 8;
    int t0 = tc * rows_per;
    int t1 = t0 + rows_per; if (t1 > T) t1 = T;
    const float* hp = hidden + ((size_t)b * T + t0) * 512 + d;
    float s0 = 0.f, s1 = 0.f, s2 = 0.f, s3 = 0.f;
    int nt = t1 - t0, t = 0;
    for (; t + 4 <= nt; t += 4) {
        s0 += hp[(size_t)(t + 0) * 512]; s1 += hp[(size_t)(t + 1) * 512];
        s2 += hp[(size_t)(t + 2) * 512]; s3 += hp[(size_t)(t + 3) * 512];
    }
    float s = (s0 + s1) + (s2 + s3);
    for (; t < nt; t++) s += hp[(size_t)t * 512];
    g_pool8[((size_t)b * 8 + tc) * 512 + d] = s;
}

// ---------------- K2: query[b][d] = (mean @ W + bias)[d] ----------------
__global__ void k_query(const float* __restrict__ W, const float* __restrict__ bias, int T) {
    __shared__ float p[512];
    int b = blockIdx.x, tid = threadIdx.x;          // 256 threads
    float invT = 1.0f / (float)T;
    for (int i = tid; i < 512; i += 256) {
        float s = 0.f;
#pragma unroll
        for (int tc = 0; tc < 8; tc++) s += g_pool8[((size_t)b * 8 + tc) * 512 + i];
        p[i] = s * invT;
    }
    __syncthreads();
    int d = tid * 2;
    float a0 = 0.f, a1 = 0.f;
#pragma unroll 16
    for (int k = 0; k < 512; k++) {
        float2 wv = *reinterpret_cast<const float2*>(W + (size_t)k * 512 + d);
        float pv = p[k];
        a0 += pv * wv.x; a1 += pv * wv.y;
    }
    g_query[(size_t)b * 512 + d]     = a0 + bias[d];
    g_query[(size_t)b * 512 + d + 1] = a1 + bias[d + 1];
}

// ---------------- K3: scores GEMM via mma.sync tf32; epilogue writes block maxes ----------------
#define KSTR 20
__global__ void __launch_bounds__(128) k_scores(const float* __restrict__ keys, int N) {
    __shared__ float skey[2][256 * KSTR];   // 40960 B
    __shared__ float sqry[2][32 * KSTR];    //  5120 B
    __shared__ unsigned int s_max[32];
    int tid = threadIdx.x, lane = tid & 31, w = tid >> 5;
    int g = lane >> 2, tg = lane & 3;
    int n0 = blockIdx.x * 256;
    if (tid < 32) s_max[tid] = 0u;

    float d[2][8][4];
#pragma unroll
    for (int mt = 0; mt < 2; mt++)
#pragma unroll
        for (int nt = 0; nt < 8; nt++)
#pragma unroll
            for (int r = 0; r < 4; r++) d[mt][nt][r] = 0.f;

#define LOAD_CHUNK(CH, BUF)                                                       \
    do {                                                                          \
        int c0_ = (CH) * 16;                                                      \
        _Pragma("unroll")                                                         \
        for (int it = 0; it < 8; it++) {                                          \
            int v = it * 128 + tid;                                               \
            int row = v >> 2, g16 = v & 3;                                        \
            int n = n0 + row; if (n >= N) n = N - 1;                              \
            cp_async16(&skey[BUF][row * KSTR + g16 * 4],                          \
                       keys + (size_t)n * 512 + c0_ + g16 * 4);                   \
        }                                                                         \
        {                                                                         \
            int row = tid >> 2, g16 = tid & 3;                                    \
            cp_async16(&sqry[BUF][row * KSTR + g16 * 4],                          \
                       g_query + (size_t)row * 512 + c0_ + g16 * 4);              \
        }                                                                         \
        asm volatile("cp.async.commit_group;" ::: "memory");                      \
    } while (0)

    LOAD_CHUNK(0, 0);
    for (int ch = 0; ch < 32; ch++) {
        int buf = ch & 1;
        if (ch + 1 < 32) {
            LOAD_CHUNK(ch + 1, (ch + 1) & 1);
            asm volatile("cp.async.wait_group 1;" ::: "memory");
        } else {
            asm volatile("cp.async.wait_group 0;" ::: "memory");
        }
        __syncthreads();

#pragma unroll
        for (int ks = 0; ks < 2; ks++) {
            unsigned int a[2][4];
#pragma unroll
            for (int mt = 0; mt < 2; mt++) {
                int qr = mt * 16 + g;
                a[mt][0] = __float_as_uint(sqry[buf][qr * KSTR + ks * 8 + tg]);
                a[mt][1] = __float_as_uint(sqry[buf][(qr + 8) * KSTR + ks * 8 + tg]);
                a[mt][2] = __float_as_uint(sqry[buf][qr * KSTR + ks * 8 + tg + 4]);
                a[mt][3] = __float_as_uint(sqry[buf][(qr + 8) * KSTR + ks * 8 + tg + 4]);
            }
#pragma unroll
            for (int nt = 0; nt < 8; nt++) {
                int kr = w * 64 + nt * 8 + g;
                unsigned int b[2];
                b[0] = __float_as_uint(skey[buf][kr * KSTR + ks * 8 + tg]);
                b[1] = __float_as_uint(skey[buf][kr * KSTR + ks * 8 + tg + 4]);
                mma_tf32(d[0][nt], a[0], b);
                mma_tf32(d[1][nt], a[1], b);
            }
        }
        __syncthreads();
    }

#pragma unroll
    for (int mt = 0; mt < 2; mt++) {
        unsigned int m0 = 0u, m1 = 0u;
        int q0 = mt * 16 + g, q1 = q0 + 8;
#pragma unroll
        for (int nt = 0; nt < 8; nt++) {
            int key = n0 + w * 64 + nt * 8 + tg * 2;
            float v0 = d[mt][nt][0] * INV_SQRT_D;
            float v1 = d[mt][nt][1] * INV_SQRT_D;
            float v2 = d[mt][nt][2] * INV_SQRT_D;
            float v3 = d[mt][nt][3] * INV_SQRT_D;
            if (key + 1 < N) {
                *reinterpret_cast<float2*>(g_scores + (size_t)q0 * N + key) = make_float2(v0, v1);
                *reinterpret_cast<float2*>(g_scores + (size_t)q1 * N + key) = make_float2(v2, v3);
                unsigned int u;
                u = fmono(v0); if (u > m0) m0 = u;
                u = fmono(v1); if (u > m0) m0 = u;
                u = fmono(v2); if (u > m1) m1 = u;
                u = fmono(v3); if (u > m1) m1 = u;
            } else if (key < N) {
                g_scores[(size_t)q0 * N + key] = v0;
                g_scores[(size_t)q1 * N + key] = v2;
                unsigned int u;
                u = fmono(v0); if (u > m0) m0 = u;
                u = fmono(v2); if (u > m1) m1 = u;
            }
        }
        atomicMax(&s_max[q0], m0);
        atomicMax(&s_max[q1], m1);
    }
    __syncthreads();
    if (tid < 32) g_bmax[tid * MAXNB + blockIdx.x] = s_max[tid];
}

// ---------------- K4: per-row tau from block maxes, scan only active blocks ----------------
__global__ void k_select(const int* __restrict__ pmk, int N, int NB) {
    __shared__ unsigned int hist[4096];
    __shared__ unsigned int seg[256], pref[256];
    __shared__ int blist[MAXNB];
    __shared__ int bcount;
    __shared__ unsigned int tau;
    int row = blockIdx.x, tid = threadIdx.x;   // 256 threads
    for (int i = tid; i < 4096; i += 256) hist[i] = 0u;
    if (tid == 0) { bcount = 0; tau = 0u; }
    __syncthreads();

    // histogram the NB block maxes by 12-bit monotone bin
    for (int b = tid; b < NB; b += 256)
        atomicAdd(&hist[g_bmax[row * MAXNB + b] >> 20], 1u);
    __syncthreads();

    // cum-from-top to find tau bin: #blockmax with bin >= tau >= mk
    unsigned int s = 0;
#pragma unroll 4
    for (int k = 0; k < 16; k++) s += hist[4095 - (tid * 16 + k)];
    seg[tid] = s;
    __syncthreads();
    if (tid == 0) {
        unsigned int run = 0;
        for (int i = 0; i < 256; i++) { pref[i] = run; run += seg[i]; }
    }
    __syncthreads();
    int mk = *pmk; if (mk < 1) mk = 1; if (mk > NB) mk = NB;
    unsigned int need = (unsigned int)mk;
    if (pref[tid] < need && pref[tid] + seg[tid] >= need) {
        unsigned int cum = pref[tid];
        for (int k = 0; k < 16; k++) {
            int bin = 4095 - (tid * 16 + k);
            cum += hist[bin];
            if (cum >= need) { tau = (unsigned int)bin; break; }
        }
    }
    __syncthreads();
    unsigned int tb = tau;

    // active block list
    for (int b = tid; b < NB; b += 256)
        if ((g_bmax[row * MAXNB + b] >> 20) >= tb)
            blist[atomicAdd(&bcount, 1)] = b;
    __syncthreads();

    // scan only active blocks' score segments
    const float* sr = g_scores + (size_t)row * N;
    int nact = bcount;
    for (int i = 0; i < nact; i++) {
        int idx = blist[i] * 256 + tid;
        if (idx < N) {
            unsigned int u = fmono(sr[idx]);
            if ((u >> 20) >= tb) {
                int pos = atomicAdd(&g_ccount[row], 1);
                if (pos < CAP) {
                    g_cu  [row * CAP + pos] = u;
                    g_cidx[row * CAP + pos] = idx;
                }
            }
        }
    }
}

// ---------------- K5: coarse top-SEL, exact rescore of SEL, exact rank, softmax, gather ----------------
__global__ void k_final(const float* __restrict__ pool_params, const float* __restrict__ keys,
                        const int* __restrict__ pkd, float* __restrict__ out, int N) {
    __shared__ unsigned int cu[CAP];
    __shared__ int          ci[CAP];
    __shared__ float        q[512];
    __shared__ int          sI[SEL];      // coarse top-SEL candidate indices
    __shared__ float        sE[SEL];      // exact scores of those
    __shared__ float        selS[64];
    __shared__ int          selI[64];
    __shared__ float        w[64];
    int row = blockIdx.x;
    int c   = g_ccount[row]; if (c > CAP) c = CAP;
    for (int i = threadIdx.x; i < c; i += 256) {
        cu[i] = g_cu  [row * CAP + i];
        ci[i] = g_cidx[row * CAP + i];
    }
    for (int i = threadIdx.x; i < 512; i += 256) q[i] = g_query[(size_t)row * 512 + i];
    __syncthreads();

    // coarse rank: (coarse desc, index asc)
    int nsel = c < SEL ? c : SEL;
    for (int i = threadIdx.x; i < c; i += 256) {
        unsigned int ui = cu[i];
        int idi = ci[i];
        int r = 0;
        for (int j = 0; j < c; j++) {
            unsigned int uj = cu[j];
            r += (uj > ui) || (uj == ui && ci[j] < idi);
        }
        if (r < SEL) sI[r] = idi;
    }
    __syncthreads();

    // exact fp32 rescore of the coarse top-SEL: one warp per candidate
    int lane = threadIdx.x & 31, wrp = threadIdx.x >> 5;
    for (int cand = wrp; cand < nsel; cand += 8) {
        const float* kr = keys + (size_t)sI[cand] * 512;
        float s = 0.f;
#pragma unroll 4
        for (int k = lane; k < 512; k += 32) s += kr[k] * q[k];
#pragma unroll
        for (int o = 16; o; o >>= 1) s += __shfl_xor_sync(0xffffffffu, s, o);
        if (lane == 0) sE[cand] = s * INV_SQRT_D;
    }
    __syncthreads();

    // exact rank among nsel: (score desc, index asc) = jax.lax.top_k order
    if (threadIdx.x < (unsigned)nsel) {
        float si = sE[threadIdx.x]; int idi = sI[threadIdx.x];
        int r = 0;
        for (int j = 0; j < nsel; j++) {
            float sj = sE[j];
            r += (sj > si) || (sj == si && sI[j] < idi);
        }
        if (r < 64) { selS[r] = si; selI[r] = idi; }
    }
    __syncthreads();
    int kd = *pkd; if (kd > 64) kd = 64; if (kd < 1) kd = 1;
    if (kd > nsel) kd = nsel;
    if (threadIdx.x == 0) {
        float mx = selS[0];
        float sum = 0.f;
        for (int r = 0; r < kd; r++) { float e = expf(selS[r] - mx); w[r] = e; sum += e; }
        float inv = 1.0f / sum;
        for (int r = 0; r < kd; r++) w[r] *= inv;
    }
    __syncthreads();
    for (int d = threadIdx.x; d < 512; d += 256) {
        float acc = 0.f;
        for (int r = 0; r < kd; r++)
            acc += w[r] * pool_params[(size_t)selI[r] * 512 + d];
        out[row * 512 + d] = acc;
    }
}

// ---------------- launch ----------------
extern "C" void kernel_launch(void* const* d_in, const int* in_sizes, int n_in,
                              void* d_out, int out_size) {
    const float* hidden      = (const float*)d_in[0];
    const float* pool_params = (const float*)d_in[1];
    const float* pool_keys   = (const float*)d_in[2];
    const float* W           = (const float*)d_in[3];
    const float* bias        = (const float*)d_in[4];
    const int*   pkd         = (const int*)d_in[5];
    const int*   pmk         = (const int*)d_in[6];

    int B = out_size / 512;          if (B > MAXB) B = MAXB;
    int T = in_sizes[0] / (B * 512);
    int N = in_sizes[2] / 512;       if (N > MAXN) N = MAXN;
    int NB = (N + 255) / 256;

    k_zero<<<1, 32>>>();
    k_mean<<<dim3(B, 8), 512>>>(hidden, T);
    k_query<<<B, 256>>>(W, bias, T);
    k_scores<<<NB, 128>>>(pool_keys, N);
    k_select<<<B, 256>>>(pmk, N, NB);
    k_final<<<B, 256>>>(pool_params, pool_keys, pkd, (float*)d_out, N);
}

// round 14
// speedup vs baseline: 4.1176x; 1.0046x over previous
#include <cuda_runtime.h>
#include <cuda_bf16.h>
#include <cstdint>

// ---------------- scratch (static __device__, no allocation) ----------------
#define MAXB 32
#define MAXN 500000
#define CAP  4096
#define SEL  96      // coarse top-SEL get exact fp32 rescore (64 + 32 slack)
#define MAXNB 2048   // max score blocks per row (ceil(500000/256)=1954)
#define CBLK 16      // score-blocks per collect CTA

__device__ float        g_pool8 [MAXB * 8 * 512];
__device__ float        g_query [MAXB * 512];            // [query b][K-dim]
__device__ float        g_scores[(size_t)MAXB * MAXN];   // 64 MB (coarse tf32 scores)
__device__ unsigned int g_bmax  [MAXB * MAXNB];          // per-row per-block max (mono)
__device__ unsigned int g_thresh[MAXB];
__device__ int          g_ccount[MAXB];
__device__ unsigned int g_cu    [MAXB * CAP];
__device__ int          g_cidx  [MAXB * CAP];

__device__ __forceinline__ unsigned int fmono(float f) {
    unsigned int u = __float_as_uint(f);
    return (u & 0x80000000u) ? ~u : (u | 0x80000000u);
}

__device__ __forceinline__ void cp_async16(void* smem_dst, const void* gmem_src) {
    unsigned int d = (unsigned int)__cvta_generic_to_shared(smem_dst);
    asm volatile("cp.async.cg.shared.global [%0], [%1], 16;" :: "r"(d), "l"(gmem_src));
}

// tf32 warp MMA: D(16x8) += A(16x8) * B(8x8); A row-major, B col-major.
__device__ __forceinline__ void mma_tf32(float d[4], const unsigned int a[4],
                                         const unsigned int b[2]) {
    asm volatile(
        "mma.sync.aligned.m16n8k8.row.col.f32.tf32.tf32.f32 "
        "{%0,%1,%2,%3}, {%4,%5,%6,%7}, {%8,%9}, {%0,%1,%2,%3};"
        : "+f"(d[0]), "+f"(d[1]), "+f"(d[2]), "+f"(d[3])
        : "r"(a[0]), "r"(a[1]), "r"(a[2]), "r"(a[3]), "r"(b[0]), "r"(b[1]));
}

#define INV_SQRT_D 0.04419417382415922f   // 1/sqrt(512)

// ---------------- K1: partial mean over T chunks ----------------
__global__ void k_mean(const float* __restrict__ hidden, int T) {
    int b  = blockIdx.x;
    int tc = blockIdx.y;              // 8 chunks
    int d  = threadIdx.x;             // 512 threads
    int rows_per = (T + 7) / 8;
    int t0 = tc * rows_per;
    int t1 = t0 + rows_per; if (t1 > T) t1 = T;
    const float* hp = hidden + ((size_t)b * T + t0) * 512 + d;
    float s0 = 0.f, s1 = 0.f, s2 = 0.f, s3 = 0.f;
    int nt = t1 - t0, t = 0;
    for (; t + 4 <= nt; t += 4) {
        s0 += hp[(size_t)(t + 0) * 512]; s1 += hp[(size_t)(t + 1) * 512];
        s2 += hp[(size_t)(t + 2) * 512]; s3 += hp[(size_t)(t + 3) * 512];
    }
    float s = (s0 + s1) + (s2 + s3);
    for (; t < nt; t++) s += hp[(size_t)t * 512];
    g_pool8[((size_t)b * 8 + tc) * 512 + d] = s;
}

// ---------------- K2: query[b][d] = (mean @ W + bias)[d] ----------------
__global__ void k_query(const float* __restrict__ W, const float* __restrict__ bias, int T) {
    __shared__ float p[512];
    int b = blockIdx.x, tid = threadIdx.x;          // 256 threads
    float invT = 1.0f / (float)T;
    for (int i = tid; i < 512; i += 256) {
        float s = 0.f;
#pragma unroll
        for (int tc = 0; tc < 8; tc++) s += g_pool8[((size_t)b * 8 + tc) * 512 + i];
        p[i] = s * invT;
    }
    __syncthreads();
    int d = tid * 2;
    float a0 = 0.f, a1 = 0.f;
#pragma unroll 16
    for (int k = 0; k < 512; k++) {
        float2 wv = *reinterpret_cast<const float2*>(W + (size_t)k * 512 + d);
        float pv = p[k];
        a0 += pv * wv.x; a1 += pv * wv.y;
    }
    g_query[(size_t)b * 512 + d]     = a0 + bias[d];
    g_query[(size_t)b * 512 + d + 1] = a1 + bias[d + 1];
}

// ---------------- K3: scores GEMM via mma.sync tf32; epilogue writes block maxes ----------------
#define KSTR 20
__global__ void __launch_bounds__(128) k_scores(const float* __restrict__ keys, int N) {
    __shared__ float skey[2][256 * KSTR];   // 40960 B
    __shared__ float sqry[2][32 * KSTR];    //  5120 B
    __shared__ unsigned int s_max[32];
    int tid = threadIdx.x, lane = tid & 31, w = tid >> 5;
    int g = lane >> 2, tg = lane & 3;
    int n0 = blockIdx.x * 256;
    if (tid < 32) s_max[tid] = 0u;

    float d[2][8][4];
#pragma unroll
    for (int mt = 0; mt < 2; mt++)
#pragma unroll
        for (int nt = 0; nt < 8; nt++)
#pragma unroll
            for (int r = 0; r < 4; r++) d[mt][nt][r] = 0.f;

#define LOAD_CHUNK(CH, BUF)                                                       \
    do {                                                                          \
        int c0_ = (CH) * 16;                                                      \
        _Pragma("unroll")                                                         \
        for (int it = 0; it < 8; it++) {                                          \
            int v = it * 128 + tid;                                               \
            int row = v >> 2, g16 = v & 3;                                        \
            int n = n0 + row; if (n >= N) n = N - 1;                              \
            cp_async16(&skey[BUF][row * KSTR + g16 * 4],                          \
                       keys + (size_t)n * 512 + c0_ + g16 * 4);                   \
        }                                                                         \
        {                                                                         \
            int row = tid >> 2, g16 = tid & 3;                                    \
            cp_async16(&sqry[BUF][row * KSTR + g16 * 4],                          \
                       g_query + (size_t)row * 512 + c0_ + g16 * 4);              \
        }                                                                         \
        asm volatile("cp.async.commit_group;" ::: "memory");                      \
    } while (0)

    LOAD_CHUNK(0, 0);
    for (int ch = 0; ch < 32; ch++) {
        int buf = ch & 1;
        if (ch + 1 < 32) {
            LOAD_CHUNK(ch + 1, (ch + 1) & 1);
            asm volatile("cp.async.wait_group 1;" ::: "memory");
        } else {
            asm volatile("cp.async.wait_group 0;" ::: "memory");
        }
        __syncthreads();

#pragma unroll
        for (int ks = 0; ks < 2; ks++) {
            unsigned int a[2][4];
#pragma unroll
            for (int mt = 0; mt < 2; mt++) {
                int qr = mt * 16 + g;
                a[mt][0] = __float_as_uint(sqry[buf][qr * KSTR + ks * 8 + tg]);
                a[mt][1] = __float_as_uint(sqry[buf][(qr + 8) * KSTR + ks * 8 + tg]);
                a[mt][2] = __float_as_uint(sqry[buf][qr * KSTR + ks * 8 + tg + 4]);
                a[mt][3] = __float_as_uint(sqry[buf][(qr + 8) * KSTR + ks * 8 + tg + 4]);
            }
#pragma unroll
            for (int nt = 0; nt < 8; nt++) {
                int kr = w * 64 + nt * 8 + g;
                unsigned int b[2];
                b[0] = __float_as_uint(skey[buf][kr * KSTR + ks * 8 + tg]);
                b[1] = __float_as_uint(skey[buf][kr * KSTR + ks * 8 + tg + 4]);
                mma_tf32(d[0][nt], a[0], b);
                mma_tf32(d[1][nt], a[1], b);
            }
        }
        __syncthreads();
    }

#pragma unroll
    for (int mt = 0; mt < 2; mt++) {
        unsigned int m0 = 0u, m1 = 0u;
        int q0 = mt * 16 + g, q1 = q0 + 8;
#pragma unroll
        for (int nt = 0; nt < 8; nt++) {
            int key = n0 + w * 64 + nt * 8 + tg * 2;
            float v0 = d[mt][nt][0] * INV_SQRT_D;
            float v1 = d[mt][nt][1] * INV_SQRT_D;
            float v2 = d[mt][nt][2] * INV_SQRT_D;
            float v3 = d[mt][nt][3] * INV_SQRT_D;
            if (key + 1 < N) {
                *reinterpret_cast<float2*>(g_scores + (size_t)q0 * N + key) = make_float2(v0, v1);
                *reinterpret_cast<float2*>(g_scores + (size_t)q1 * N + key) = make_float2(v2, v3);
                unsigned int u;
                u = fmono(v0); if (u > m0) m0 = u;
                u = fmono(v1); if (u > m0) m0 = u;
                u = fmono(v2); if (u > m1) m1 = u;
                u = fmono(v3); if (u > m1) m1 = u;
            } else if (key < N) {
                g_scores[(size_t)q0 * N + key] = v0;
                g_scores[(size_t)q1 * N + key] = v2;
                unsigned int u;
                u = fmono(v0); if (u > m0) m0 = u;
                u = fmono(v2); if (u > m1) m1 = u;
            }
        }
        atomicMax(&s_max[q0], m0);
        atomicMax(&s_max[q1], m1);
    }
    __syncthreads();
    if (tid < 32) g_bmax[tid * MAXNB + blockIdx.x] = s_max[tid];
}

// ---------------- K4: per-row tau from block-max histogram (32 tiny CTAs) ----------------
__global__ void k_tau(const int* __restrict__ pmk, int NB) {
    __shared__ unsigned int hist[4096];
    __shared__ unsigned int seg[256], pref[256];
    int row = blockIdx.x, tid = threadIdx.x;   // 256 threads
    for (int i = tid; i < 4096; i += 256) hist[i] = 0u;
    __syncthreads();
    for (int b = tid; b < NB; b += 256)
        atomicAdd(&hist[g_bmax[row * MAXNB + b] >> 20], 1u);
    __syncthreads();
    unsigned int s = 0;
#pragma unroll 4
    for (int k = 0; k < 16; k++) s += hist[4095 - (tid * 16 + k)];
    seg[tid] = s;
    __syncthreads();
    if (tid == 0) {
        unsigned int run = 0;
        for (int i = 0; i < 256; i++) { pref[i] = run; run += seg[i]; }
        g_ccount[row] = 0;
    }
    __syncthreads();
    int mk = *pmk; if (mk < 1) mk = 1; if (mk > NB) mk = NB;
    unsigned int need = (unsigned int)mk;
    if (pref[tid] < need && pref[tid] + seg[tid] >= need) {
        unsigned int cum = pref[tid];
        for (int k = 0; k < 16; k++) {
            int bin = 4095 - (tid * 16 + k);
            cum += hist[bin];
            if (cum >= need) { g_thresh[row] = (unsigned int)bin; break; }
        }
    }
}

// ---------------- K5: parallel pruned collect — grid (ceil(NB/CBLK), B) ----------------
__global__ void k_collect(int N, int NB) {
    int row = blockIdx.y, tid = threadIdx.x;   // 256 threads
    unsigned int tb = g_thresh[row];
    int b0 = blockIdx.x * CBLK;
    const float* sr = g_scores + (size_t)row * N;
#pragma unroll
    for (int bb = 0; bb < CBLK; bb++) {
        int b = b0 + bb;
        if (b >= NB) break;
        if ((g_bmax[row * MAXNB + b] >> 20) < tb) continue;   // pruned: ~88% skip
        int idx = b * 256 + tid;
        if (idx < N) {
            unsigned int u = fmono(sr[idx]);
            if ((u >> 20) >= tb) {
                int pos = atomicAdd(&g_ccount[row], 1);
                if (pos < CAP) {
                    g_cu  [row * CAP + pos] = u;
                    g_cidx[row * CAP + pos] = idx;
                }
            }
        }
    }
}

// ---------------- K6: coarse top-SEL, exact rescore of SEL, exact rank, softmax, gather ----------------
__global__ void k_final(const float* __restrict__ pool_params, const float* __restrict__ keys,
                        const int* __restrict__ pkd, float* __restrict__ out, int N) {
    __shared__ unsigned int cu[CAP];
    __shared__ int          ci[CAP];
    __shared__ float        q[512];
    __shared__ int          sI[SEL];      // coarse top-SEL candidate indices
    __shared__ float        sE[SEL];      // exact scores of those
    __shared__ float        selS[64];
    __shared__ int          selI[64];
    __shared__ float        w[64];
    int row = blockIdx.x;
    int c   = g_ccount[row]; if (c > CAP) c = CAP;
    for (int i = threadIdx.x; i < c; i += 256) {
        cu[i] = g_cu  [row * CAP + i];
        ci[i] = g_cidx[row * CAP + i];
    }
    for (int i = threadIdx.x; i < 512; i += 256) q[i] = g_query[(size_t)row * 512 + i];
    __syncthreads();

    // coarse rank: (coarse desc, index asc)
    int nsel = c < SEL ? c : SEL;
    for (int i = threadIdx.x; i < c; i += 256) {
        unsigned int ui = cu[i];
        int idi = ci[i];
        int r = 0;
        for (int j = 0; j < c; j++) {
            unsigned int uj = cu[j];
            r += (uj > ui) || (uj == ui && ci[j] < idi);
        }
        if (r < SEL) sI[r] = idi;
    }
    __syncthreads();

    // exact fp32 rescore of the coarse top-SEL: one warp per candidate
    int lane = threadIdx.x & 31, wrp = threadIdx.x >> 5;
    for (int cand = wrp; cand < nsel; cand += 8) {
        const float* kr = keys + (size_t)sI[cand] * 512;
        float s = 0.f;
#pragma unroll 4
        for (int k = lane; k < 512; k += 32) s += kr[k] * q[k];
#pragma unroll
        for (int o = 16; o; o >>= 1) s += __shfl_xor_sync(0xffffffffu, s, o);
        if (lane == 0) sE[cand] = s * INV_SQRT_D;
    }
    __syncthreads();

    // exact rank among nsel: (score desc, index asc) = jax.lax.top_k order
    if (threadIdx.x < (unsigned)nsel) {
        float si = sE[threadIdx.x]; int idi = sI[threadIdx.x];
        int r = 0;
        for (int j = 0; j < nsel; j++) {
            float sj = sE[j];
            r += (sj > si) || (sj == si && sI[j] < idi);
        }
        if (r < 64) { selS[r] = si; selI[r] = idi; }
    }
    __syncthreads();
    int kd = *pkd; if (kd > 64) kd = 64; if (kd < 1) kd = 1;
    if (kd > nsel) kd = nsel;
    if (threadIdx.x == 0) {
        float mx = selS[0];
        float sum = 0.f;
        for (int r = 0; r < kd; r++) { float e = expf(selS[r] - mx); w[r] = e; sum += e; }
        float inv = 1.0f / sum;
        for (int r = 0; r < kd; r++) w[r] *= inv;
    }
    __syncthreads();
    for (int d = threadIdx.x; d < 512; d += 256) {
        float acc = 0.f;
        for (int r = 0; r < kd; r++)
            acc += w[r] * pool_params[(size_t)selI[r] * 512 + d];
        out[row * 512 + d] = acc;
    }
}

// ---------------- launch ----------------
extern "C" void kernel_launch(void* const* d_in, const int* in_sizes, int n_in,
                              void* d_out, int out_size) {
    const float* hidden      = (const float*)d_in[0];
    const float* pool_params = (const float*)d_in[1];
    const float* pool_keys   = (const float*)d_in[2];
    const float* W           = (const float*)d_in[3];
    const float* bias        = (const float*)d_in[4];
    const int*   pkd         = (const int*)d_in[5];
    const int*   pmk         = (const int*)d_in[6];

    int B = out_size / 512;          if (B > MAXB) B = MAXB;
    int T = in_sizes[0] / (B * 512);
    int N = in_sizes[2] / 512;       if (N > MAXN) N = MAXN;
    int NB = (N + 255) / 256;

    k_mean<<<dim3(B, 8), 512>>>(hidden, T);
    k_query<<<B, 256>>>(W, bias, T);
    k_scores<<<NB, 128>>>(pool_keys, N);
    k_tau<<<B, 256>>>(pmk, NB);
    k_collect<<<dim3((NB + CBLK - 1) / CBLK, B), 256>>>(N, NB);
    k_final<<<B, 256>>>(pool_params, pool_keys, pkd, (float*)d_out, N);
}

// round 15
// speedup vs baseline: 4.9331x; 1.1980x over previous
#include <cuda_runtime.h>
#include <cuda_bf16.h>
#include <cstdint>

// ---------------- scratch (static __device__, no allocation) ----------------
#define MAXB 32
#define MAXN 500000
#define SEL  96      // coarse top-SEL get exact fp32 rescore (64 + 32 slack)
#define MAXNB 2048   // max score blocks per row (ceil(500000/256)=1954)
#define BLCAP 1280   // active-block list cap
#define CCAP  3072   // candidate cap

__device__ float          g_pool8 [MAXB * 8 * 512];
__device__ float          g_query [MAXB * 512];            // [query b][K-dim]
__device__ unsigned short g_scb   [(size_t)MAXB * MAXN];   // 32 MB coarse bf16 scores
__device__ unsigned int   g_bmax  [MAXB * MAXNB];          // per-row per-block max (mono16)

__device__ __forceinline__ unsigned short mono16(unsigned short h) {
    return (h & 0x8000u) ? (unsigned short)~h : (unsigned short)(h | 0x8000u);
}
__device__ __forceinline__ void cp_async16(void* smem_dst, const void* gmem_src) {
    unsigned int d = (unsigned int)__cvta_generic_to_shared(smem_dst);
    asm volatile("cp.async.cg.shared.global [%0], [%1], 16;" :: "r"(d), "l"(gmem_src));
}

// tf32 warp MMA: D(16x8) += A(16x8) * B(8x8); A row-major, B col-major.
__device__ __forceinline__ void mma_tf32(float d[4], const unsigned int a[4],
                                         const unsigned int b[2]) {
    asm volatile(
        "mma.sync.aligned.m16n8k8.row.col.f32.tf32.tf32.f32 "
        "{%0,%1,%2,%3}, {%4,%5,%6,%7}, {%8,%9}, {%0,%1,%2,%3};"
        : "+f"(d[0]), "+f"(d[1]), "+f"(d[2]), "+f"(d[3])
        : "r"(a[0]), "r"(a[1]), "r"(a[2]), "r"(a[3]), "r"(b[0]), "r"(b[1]));
}

#define INV_SQRT_D 0.04419417382415922f   // 1/sqrt(512)

// ---------------- K1: partial mean over T chunks ----------------
__global__ void k_mean(const float* __restrict__ hidden, int T) {
    int b  = blockIdx.x;
    int tc = blockIdx.y;              // 8 chunks
    int d  = threadIdx.x;             // 512 threads
    int rows_per = (T + 7) / 8;
    int t0 = tc * rows_per;
    int t1 = t0 + rows_per; if (t1 > T) t1 = T;
    const float* hp = hidden + ((size_t)b * T + t0) * 512 + d;
    float s0 = 0.f, s1 = 0.f, s2 = 0.f, s3 = 0.f;
    int nt = t1 - t0, t = 0;
    for (; t + 4 <= nt; t += 4) {
        s0 += hp[(size_t)(t + 0) * 512]; s1 += hp[(size_t)(t + 1) * 512];
        s2 += hp[(size_t)(t + 2) * 512]; s3 += hp[(size_t)(t + 3) * 512];
    }
    float s = (s0 + s1) + (s2 + s3);
    for (; t < nt; t++) s += hp[(size_t)t * 512];
    g_pool8[((size_t)b * 8 + tc) * 512 + d] = s;
}

// ---------------- K2: query[b][d] = (mean @ W + bias)[d] ----------------
__global__ void k_query(const float* __restrict__ W, const float* __restrict__ bias, int T) {
    __shared__ float p[512];
    int b = blockIdx.x, tid = threadIdx.x;          // 256 threads
    float invT = 1.0f / (float)T;
    for (int i = tid; i < 512; i += 256) {
        float s = 0.f;
#pragma unroll
        for (int tc = 0; tc < 8; tc++) s += g_pool8[((size_t)b * 8 + tc) * 512 + i];
        p[i] = s * invT;
    }
    __syncthreads();
    int d = tid * 2;
    float a0 = 0.f, a1 = 0.f;
#pragma unroll 16
    for (int k = 0; k < 512; k++) {
        float2 wv = *reinterpret_cast<const float2*>(W + (size_t)k * 512 + d);
        float pv = p[k];
        a0 += pv * wv.x; a1 += pv * wv.y;
    }
    g_query[(size_t)b * 512 + d]     = a0 + bias[d];
    g_query[(size_t)b * 512 + d + 1] = a1 + bias[d + 1];
}

// ---------------- K3: scores GEMM via mma.sync tf32; bf16 stores + mono16 blockmax ----------------
#define KSTR 20
__global__ void __launch_bounds__(128) k_scores(const float* __restrict__ keys, int N) {
    __shared__ float skey[2][256 * KSTR];   // 40960 B
    __shared__ float sqry[2][32 * KSTR];    //  5120 B
    __shared__ unsigned int s_max[32];
    int tid = threadIdx.x, lane = tid & 31, w = tid >> 5;
    int g = lane >> 2, tg = lane & 3;
    int n0 = blockIdx.x * 256;
    if (tid < 32) s_max[tid] = 0u;

    float d[2][8][4];
#pragma unroll
    for (int mt = 0; mt < 2; mt++)
#pragma unroll
        for (int nt = 0; nt < 8; nt++)
#pragma unroll
            for (int r = 0; r < 4; r++) d[mt][nt][r] = 0.f;

#define LOAD_CHUNK(CH, BUF)                                                       \
    do {                                                                          \
        int c0_ = (CH) * 16;                                                      \
        _Pragma("unroll")                                                         \
        for (int it = 0; it < 8; it++) {                                          \
            int v = it * 128 + tid;                                               \
            int row = v >> 2, g16 = v & 3;                                        \
            int n = n0 + row; if (n >= N) n = N - 1;                              \
            cp_async16(&skey[BUF][row * KSTR + g16 * 4],                          \
                       keys + (size_t)n * 512 + c0_ + g16 * 4);                   \
        }                                                                         \
        {                                                                         \
            int row = tid >> 2, g16 = tid & 3;                                    \
            cp_async16(&sqry[BUF][row * KSTR + g16 * 4],                          \
                       g_query + (size_t)row * 512 + c0_ + g16 * 4);              \
        }                                                                         \
        asm volatile("cp.async.commit_group;" ::: "memory");                      \
    } while (0)

    LOAD_CHUNK(0, 0);
    for (int ch = 0; ch < 32; ch++) {
        int buf = ch & 1;
        if (ch + 1 < 32) {
            LOAD_CHUNK(ch + 1, (ch + 1) & 1);
            asm volatile("cp.async.wait_group 1;" ::: "memory");
        } else {
            asm volatile("cp.async.wait_group 0;" ::: "memory");
        }
        __syncthreads();

#pragma unroll
        for (int ks = 0; ks < 2; ks++) {
            unsigned int a[2][4];
#pragma unroll
            for (int mt = 0; mt < 2; mt++) {
                int qr = mt * 16 + g;
                a[mt][0] = __float_as_uint(sqry[buf][qr * KSTR + ks * 8 + tg]);
                a[mt][1] = __float_as_uint(sqry[buf][(qr + 8) * KSTR + ks * 8 + tg]);
                a[mt][2] = __float_as_uint(sqry[buf][qr * KSTR + ks * 8 + tg + 4]);
                a[mt][3] = __float_as_uint(sqry[buf][(qr + 8) * KSTR + ks * 8 + tg + 4]);
            }
#pragma unroll
            for (int nt = 0; nt < 8; nt++) {
                int kr = w * 64 + nt * 8 + g;
                unsigned int b[2];
                b[0] = __float_as_uint(skey[buf][kr * KSTR + ks * 8 + tg]);
                b[1] = __float_as_uint(skey[buf][kr * KSTR + ks * 8 + tg + 4]);
                mma_tf32(d[0][nt], a[0], b);
                mma_tf32(d[1][nt], a[1], b);
            }
        }
        __syncthreads();
    }

    // epilogue: bf16 packed stores + mono16 block maxes (consistent with stored values)
#pragma unroll
    for (int mt = 0; mt < 2; mt++) {
        unsigned int m0 = 0u, m1 = 0u;
        int q0 = mt * 16 + g, q1 = q0 + 8;
#pragma unroll
        for (int nt = 0; nt < 8; nt++) {
            int key = n0 + w * 64 + nt * 8 + tg * 2;
            float v0 = d[mt][nt][0] * INV_SQRT_D;
            float v1 = d[mt][nt][1] * INV_SQRT_D;
            float v2 = d[mt][nt][2] * INV_SQRT_D;
            float v3 = d[mt][nt][3] * INV_SQRT_D;
            if (key + 1 < N) {
                __nv_bfloat162 h01 = __floats2bfloat162_rn(v0, v1);   // x=lo=v0
                __nv_bfloat162 h23 = __floats2bfloat162_rn(v2, v3);
                unsigned int p01 = *reinterpret_cast<unsigned int*>(&h01);
                unsigned int p23 = *reinterpret_cast<unsigned int*>(&h23);
                reinterpret_cast<unsigned int*>(g_scb)[((size_t)q0 * N + key) >> 1] = p01;
                reinterpret_cast<unsigned int*>(g_scb)[((size_t)q1 * N + key) >> 1] = p23;
                unsigned int u;
                u = mono16((unsigned short)(p01 & 0xFFFF)); if (u > m0) m0 = u;
                u = mono16((unsigned short)(p01 >> 16));    if (u > m0) m0 = u;
                u = mono16((unsigned short)(p23 & 0xFFFF)); if (u > m1) m1 = u;
                u = mono16((unsigned short)(p23 >> 16));    if (u > m1) m1 = u;
            } else if (key < N) {
                unsigned short h0 = __bfloat16_as_ushort(__float2bfloat16_rn(v0));
                unsigned short h2 = __bfloat16_as_ushort(__float2bfloat16_rn(v2));
                g_scb[(size_t)q0 * N + key] = h0;
                g_scb[(size_t)q1 * N + key] = h2;
                unsigned int u;
                u = mono16(h0); if (u > m0) m0 = u;
                u = mono16(h2); if (u > m1) m1 = u;
            }
        }
        atomicMax(&s_max[q0], m0);
        atomicMax(&s_max[q1], m1);
    }
    __syncthreads();
    if (tid < 32) g_bmax[tid * MAXNB + blockIdx.x] = s_max[tid];
}

// ---------------- K4: fused tau + pruned collect + rescore + softmax + gather ----------------
__global__ void __launch_bounds__(256) k_post(
        const float* __restrict__ pool_params, const float* __restrict__ keys,
        const int* __restrict__ pkd, const int* __restrict__ pmk,
        float* __restrict__ out, int N, int NB) {
    __shared__ unsigned int hist[4096];                 // 16 KB
    __shared__ unsigned int seg[256], pref[256];        //  2 KB
    __shared__ int blist[BLCAP];                        //  5 KB
    __shared__ int   cidx [CCAP];                       // 12 KB
    __shared__ unsigned short cmono[CCAP];              //  6 KB
    __shared__ float q[512];                            //  2 KB
    __shared__ int   sI[SEL];
    __shared__ float sE[SEL];
    __shared__ float selS[64];
    __shared__ int   selI[64];
    __shared__ float wgt[64];
    __shared__ int nact_s, ccount;
    __shared__ unsigned int tau_s;

    int row = blockIdx.x, tid = threadIdx.x, lane = tid & 31, wrp = tid >> 5;
    for (int i = tid; i < 4096; i += 256) hist[i] = 0u;
    if (tid == 0) { nact_s = 0; ccount = 0; tau_s = 0u; }
    for (int i = tid; i < 512; i += 256) q[i] = g_query[(size_t)row * 512 + i];
    __syncthreads();

    // 12-bit hist of block maxes
    for (int b = tid; b < NB; b += 256)
        atomicAdd(&hist[g_bmax[row * MAXNB + b] >> 4], 1u);
    __syncthreads();

    // cum-from-top segments + warp-parallel exclusive prefix
    unsigned int s = 0;
#pragma unroll 4
    for (int k = 0; k < 16; k++) s += hist[4095 - (tid * 16 + k)];
    seg[tid] = s;
    __syncthreads();
    if (tid < 32) {
        unsigned int v[8], tot = 0;
#pragma unroll
        for (int k = 0; k < 8; k++) { v[k] = seg[tid * 8 + k]; tot += v[k]; }
        unsigned int sc = tot;
#pragma unroll
        for (int o = 1; o < 32; o <<= 1) {
            unsigned int t = __shfl_up_sync(0xffffffffu, sc, o);
            if (lane >= o) sc += t;
        }
        unsigned int base = sc - tot;
#pragma unroll
        for (int k = 0; k < 8; k++) { pref[tid * 8 + k] = base; base += v[k]; }
    }
    __syncthreads();
    int mk = *pmk; if (mk < 1) mk = 1; if (mk > NB) mk = NB;
    unsigned int need = (unsigned int)mk;
    if (pref[tid] < need && pref[tid] + seg[tid] >= need) {
        unsigned int cum = pref[tid];
        for (int k = 0; k < 16; k++) {
            int bin = 4095 - (tid * 16 + k);
            cum += hist[bin];
            if (cum >= need) { tau_s = (unsigned int)bin; break; }
        }
    }
    __syncthreads();
    unsigned int tb = tau_s;

    // active block list
    for (int b = tid; b < NB; b += 256)
        if ((g_bmax[row * MAXNB + b] >> 4) >= tb) {
            int p = atomicAdd(&nact_s, 1);
            if (p < BLCAP) blist[p] = b;
        }
    __syncthreads();
    int nact = nact_s; if (nact > BLCAP) nact = BLCAP;

    // collect candidates: warp per block, 4 packed (uint=2 bf16) loads per thread
    const unsigned int* sr = reinterpret_cast<const unsigned int*>(g_scb + (size_t)row * N);
    for (int i = wrp; i < nact; i += 8) {
        int b = blist[i];
#pragma unroll
        for (int j = 0; j < 4; j++) {
            int u32i = b * 128 + lane + j * 32;
            int idx0 = u32i * 2;
            if (idx0 + 1 < N) {
                unsigned int pp = sr[u32i];
                unsigned short m0 = mono16((unsigned short)(pp & 0xFFFF));
                unsigned short m1 = mono16((unsigned short)(pp >> 16));
                if ((unsigned int)(m0 >> 4) >= tb) {
                    int p = atomicAdd(&ccount, 1);
                    if (p < CCAP) { cidx[p] = idx0; cmono[p] = m0; }
                }
                if ((unsigned int)(m1 >> 4) >= tb) {
                    int p = atomicAdd(&ccount, 1);
                    if (p < CCAP) { cidx[p] = idx0 + 1; cmono[p] = m1; }
                }
            } else if (idx0 < N) {
                unsigned short m0 = mono16(g_scb[(size_t)row * N + idx0]);
                if ((unsigned int)(m0 >> 4) >= tb) {
                    int p = atomicAdd(&ccount, 1);
                    if (p < CCAP) { cidx[p] = idx0; cmono[p] = m0; }
                }
            }
        }
    }
    __syncthreads();
    int c = ccount; if (c > CCAP) c = CCAP;

    // coarse rank: (coarse desc, index asc); keep top-SEL indices
    int nsel = c < SEL ? c : SEL;
    for (int i = tid; i < c; i += 256) {
        unsigned short mi = cmono[i];
        int idi = cidx[i];
        int r = 0;
        for (int j = 0; j < c; j++) {
            unsigned short mj = cmono[j];
            r += (mj > mi) || (mj == mi && cidx[j] < idi);
        }
        if (r < SEL) sI[r] = idi;
    }
    __syncthreads();

    // exact fp32 rescore of coarse top-SEL: one warp per candidate, full-unroll MLP
    for (int cand = wrp; cand < nsel; cand += 8) {
        const float* kr = keys + (size_t)sI[cand] * 512;
        float sm = 0.f;
#pragma unroll
        for (int k = 0; k < 16; k++) sm += kr[lane + k * 32] * q[lane + k * 32];
#pragma unroll
        for (int o = 16; o; o >>= 1) sm += __shfl_xor_sync(0xffffffffu, sm, o);
        if (lane == 0) sE[cand] = sm * INV_SQRT_D;
    }
    __syncthreads();

    // exact rank among nsel: (score desc, index asc) = jax.lax.top_k order
    if (tid < nsel) {
        float si = sE[tid]; int idi = sI[tid];
        int r = 0;
        for (int j = 0; j < nsel; j++) {
            float sj = sE[j];
            r += (sj > si) || (sj == si && sI[j] < idi);
        }
        if (r < 64) { selS[r] = si; selI[r] = idi; }
    }
    __syncthreads();
    int kd = *pkd; if (kd > 64) kd = 64; if (kd < 1) kd = 1;
    if (kd > nsel) kd = nsel;
    if (tid == 0) {
        float mx = selS[0];
        float sum = 0.f;
        for (int r = 0; r < kd; r++) { float e = expf(selS[r] - mx); wgt[r] = e; sum += e; }
        float inv = 1.0f / sum;
        for (int r = 0; r < kd; r++) wgt[r] *= inv;
    }
    __syncthreads();
    for (int d = tid; d < 512; d += 256) {
        float acc = 0.f;
#pragma unroll 4
        for (int r = 0; r < kd; r++)
            acc += wgt[r] * pool_params[(size_t)selI[r] * 512 + d];
        out[row * 512 + d] = acc;
    }
}

// ---------------- launch ----------------
extern "C" void kernel_launch(void* const* d_in, const int* in_sizes, int n_in,
                              void* d_out, int out_size) {
    const float* hidden      = (const float*)d_in[0];
    const float* pool_params = (const float*)d_in[1];
    const float* pool_keys   = (const float*)d_in[2];
    const float* W           = (const float*)d_in[3];
    const float* bias        = (const float*)d_in[4];
    const int*   pkd         = (const int*)d_in[5];
    const int*   pmk         = (const int*)d_in[6];

    int B = out_size / 512;          if (B > MAXB) B = MAXB;
    int T = in_sizes[0] / (B * 512);
    int N = in_sizes[2] / 512;       if (N > MAXN) N = MAXN;
    int NB = (N + 255) / 256;

    k_mean<<<dim3(B, 8), 512>>>(hidden, T);
    k_query<<<B, 256>>>(W, bias, T);
    k_scores<<<NB, 128>>>(pool_keys, N);
    k_post<<<B, 256>>>(pool_params, pool_keys, pkd, pmk, (float*)d_out, N, NB);
}

// round 16
// speedup vs baseline: 6.2232x; 1.2615x over previous
#include <cuda_runtime.h>
#include <cuda_bf16.h>
#include <cstdint>

// ---------------- scratch (static __device__, no allocation) ----------------
#define MAXB 32
#define MAXN 500000
#define SEL  96      // coarse top-SEL get exact fp32 rescore (64 + 32 slack)
#define MAXNB 2048   // max score blocks per row (ceil(500000/256)=1954)
#define BLCAP 1280   // active-block list cap
#define CCAP  3072   // candidate cap

__device__ float          g_pool8 [MAXB * 8 * 512];
__device__ float          g_query [MAXB * 512];            // [query b][K-dim]
__device__ unsigned short g_scb   [(size_t)MAXB * MAXN];   // 32 MB coarse bf16 scores
__device__ unsigned int   g_bmax  [MAXB * MAXNB];          // per-row per-block max (mono16)

__device__ __forceinline__ unsigned short mono16(unsigned short h) {
    return (h & 0x8000u) ? (unsigned short)~h : (unsigned short)(h | 0x8000u);
}
__device__ __forceinline__ void cp_async16(void* smem_dst, const void* gmem_src) {
    unsigned int d = (unsigned int)__cvta_generic_to_shared(smem_dst);
    asm volatile("cp.async.cg.shared.global [%0], [%1], 16;" :: "r"(d), "l"(gmem_src));
}

// tf32 warp MMA: D(16x8) += A(16x8) * B(8x8); A row-major, B col-major.
__device__ __forceinline__ void mma_tf32(float d[4], const unsigned int a[4],
                                         const unsigned int b[2]) {
    asm volatile(
        "mma.sync.aligned.m16n8k8.row.col.f32.tf32.tf32.f32 "
        "{%0,%1,%2,%3}, {%4,%5,%6,%7}, {%8,%9}, {%0,%1,%2,%3};"
        : "+f"(d[0]), "+f"(d[1]), "+f"(d[2]), "+f"(d[3])
        : "r"(a[0]), "r"(a[1]), "r"(a[2]), "r"(a[3]), "r"(b[0]), "r"(b[1]));
}

#define INV_SQRT_D 0.04419417382415922f   // 1/sqrt(512)

// ---------------- K1: partial mean over T chunks ----------------
__global__ void k_mean(const float* __restrict__ hidden, int T) {
    int b  = blockIdx.x;
    int tc = blockIdx.y;              // 8 chunks
    int d  = threadIdx.x;             // 512 threads
    int rows_per = (T + 7) / 8;
    int t0 = tc * rows_per;
    int t1 = t0 + rows_per; if (t1 > T) t1 = T;
    const float* hp = hidden + ((size_t)b * T + t0) * 512 + d;
    float s0 = 0.f, s1 = 0.f, s2 = 0.f, s3 = 0.f;
    int nt = t1 - t0, t = 0;
    for (; t + 4 <= nt; t += 4) {
        s0 += hp[(size_t)(t + 0) * 512]; s1 += hp[(size_t)(t + 1) * 512];
        s2 += hp[(size_t)(t + 2) * 512]; s3 += hp[(size_t)(t + 3) * 512];
    }
    float s = (s0 + s1) + (s2 + s3);
    for (; t < nt; t++) s += hp[(size_t)t * 512];
    g_pool8[((size_t)b * 8 + tc) * 512 + d] = s;
}

// ---------------- K2: query[b][d] = (mean @ W + bias)[d] ----------------
__global__ void k_query(const float* __restrict__ W, const float* __restrict__ bias, int T) {
    __shared__ float p[512];
    int b = blockIdx.x, tid = threadIdx.x;          // 256 threads
    float invT = 1.0f / (float)T;
    for (int i = tid; i < 512; i += 256) {
        float s = 0.f;
#pragma unroll
        for (int tc = 0; tc < 8; tc++) s += g_pool8[((size_t)b * 8 + tc) * 512 + i];
        p[i] = s * invT;
    }
    __syncthreads();
    int d = tid * 2;
    float a0 = 0.f, a1 = 0.f;
#pragma unroll 16
    for (int k = 0; k < 512; k++) {
        float2 wv = *reinterpret_cast<const float2*>(W + (size_t)k * 512 + d);
        float pv = p[k];
        a0 += pv * wv.x; a1 += pv * wv.y;
    }
    g_query[(size_t)b * 512 + d]     = a0 + bias[d];
    g_query[(size_t)b * 512 + d + 1] = a1 + bias[d + 1];
}

// ---------------- K3: scores GEMM via mma.sync tf32; bf16 stores + mono16 blockmax ----------------
#define KSTR 20
__global__ void __launch_bounds__(128) k_scores(const float* __restrict__ keys, int N) {
    __shared__ float skey[2][256 * KSTR];   // 40960 B
    __shared__ float sqry[2][32 * KSTR];    //  5120 B
    __shared__ unsigned int s_max[32];
    int tid = threadIdx.x, lane = tid & 31, w = tid >> 5;
    int g = lane >> 2, tg = lane & 3;
    int n0 = blockIdx.x * 256;
    if (tid < 32) s_max[tid] = 0u;

    float d[2][8][4];
#pragma unroll
    for (int mt = 0; mt < 2; mt++)
#pragma unroll
        for (int nt = 0; nt < 8; nt++)
#pragma unroll
            for (int r = 0; r < 4; r++) d[mt][nt][r] = 0.f;

#define LOAD_CHUNK(CH, BUF)                                                       \
    do {                                                                          \
        int c0_ = (CH) * 16;                                                      \
        _Pragma("unroll")                                                         \
        for (int it = 0; it < 8; it++) {                                          \
            int v = it * 128 + tid;                                               \
            int row = v >> 2, g16 = v & 3;                                        \
            int n = n0 + row; if (n >= N) n = N - 1;                              \
            cp_async16(&skey[BUF][row * KSTR + g16 * 4],                          \
                       keys + (size_t)n * 512 + c0_ + g16 * 4);                   \
        }                                                                         \
        {                                                                         \
            int row = tid >> 2, g16 = tid & 3;                                    \
            cp_async16(&sqry[BUF][row * KSTR + g16 * 4],                          \
                       g_query + (size_t)row * 512 + c0_ + g16 * 4);              \
        }                                                                         \
        asm volatile("cp.async.commit_group;" ::: "memory");                      \
    } while (0)

    LOAD_CHUNK(0, 0);
    for (int ch = 0; ch < 32; ch++) {
        int buf = ch & 1;
        if (ch + 1 < 32) {
            LOAD_CHUNK(ch + 1, (ch + 1) & 1);
            asm volatile("cp.async.wait_group 1;" ::: "memory");
        } else {
            asm volatile("cp.async.wait_group 0;" ::: "memory");
        }
        __syncthreads();

#pragma unroll
        for (int ks = 0; ks < 2; ks++) {
            unsigned int a[2][4];
#pragma unroll
            for (int mt = 0; mt < 2; mt++) {
                int qr = mt * 16 + g;
                a[mt][0] = __float_as_uint(sqry[buf][qr * KSTR + ks * 8 + tg]);
                a[mt][1] = __float_as_uint(sqry[buf][(qr + 8) * KSTR + ks * 8 + tg]);
                a[mt][2] = __float_as_uint(sqry[buf][qr * KSTR + ks * 8 + tg + 4]);
                a[mt][3] = __float_as_uint(sqry[buf][(qr + 8) * KSTR + ks * 8 + tg + 4]);
            }
#pragma unroll
            for (int nt = 0; nt < 8; nt++) {
                int kr = w * 64 + nt * 8 + g;
                unsigned int b[2];
                b[0] = __float_as_uint(skey[buf][kr * KSTR + ks * 8 + tg]);
                b[1] = __float_as_uint(skey[buf][kr * KSTR + ks * 8 + tg + 4]);
                mma_tf32(d[0][nt], a[0], b);
                mma_tf32(d[1][nt], a[1], b);
            }
        }
        __syncthreads();
    }

    // epilogue: bf16 packed stores + mono16 block maxes (consistent with stored values)
#pragma unroll
    for (int mt = 0; mt < 2; mt++) {
        unsigned int m0 = 0u, m1 = 0u;
        int q0 = mt * 16 + g, q1 = q0 + 8;
#pragma unroll
        for (int nt = 0; nt < 8; nt++) {
            int key = n0 + w * 64 + nt * 8 + tg * 2;
            float v0 = d[mt][nt][0] * INV_SQRT_D;
            float v1 = d[mt][nt][1] * INV_SQRT_D;
            float v2 = d[mt][nt][2] * INV_SQRT_D;
            float v3 = d[mt][nt][3] * INV_SQRT_D;
            if (key + 1 < N) {
                __nv_bfloat162 h01 = __floats2bfloat162_rn(v0, v1);   // x=lo=v0
                __nv_bfloat162 h23 = __floats2bfloat162_rn(v2, v3);
                unsigned int p01 = *reinterpret_cast<unsigned int*>(&h01);
                unsigned int p23 = *reinterpret_cast<unsigned int*>(&h23);
                reinterpret_cast<unsigned int*>(g_scb)[((size_t)q0 * N + key) >> 1] = p01;
                reinterpret_cast<unsigned int*>(g_scb)[((size_t)q1 * N + key) >> 1] = p23;
                unsigned int u;
                u = mono16((unsigned short)(p01 & 0xFFFF)); if (u > m0) m0 = u;
                u = mono16((unsigned short)(p01 >> 16));    if (u > m0) m0 = u;
                u = mono16((unsigned short)(p23 & 0xFFFF)); if (u > m1) m1 = u;
                u = mono16((unsigned short)(p23 >> 16));    if (u > m1) m1 = u;
            } else if (key < N) {
                unsigned short h0 = __bfloat16_as_ushort(__float2bfloat16_rn(v0));
                unsigned short h2 = __bfloat16_as_ushort(__float2bfloat16_rn(v2));
                g_scb[(size_t)q0 * N + key] = h0;
                g_scb[(size_t)q1 * N + key] = h2;
                unsigned int u;
                u = mono16(h0); if (u > m0) m0 = u;
                u = mono16(h2); if (u > m1) m1 = u;
            }
        }
        atomicMax(&s_max[q0], m0);
        atomicMax(&s_max[q1], m1);
    }
    __syncthreads();
    if (tid < 32) g_bmax[tid * MAXNB + blockIdx.x] = s_max[tid];
}

// ---------------- K4: fused EXACT-tau + pruned collect + rescore + softmax + gather ----------------
__global__ void __launch_bounds__(256) k_post(
        const float* __restrict__ pool_params, const float* __restrict__ keys,
        const int* __restrict__ pkd, const int* __restrict__ pmk,
        float* __restrict__ out, int N, int NB) {
    __shared__ unsigned int hist[4096];                 // 16 KB
    __shared__ unsigned int seg[256], pref[256];        //  2 KB
    __shared__ unsigned int h2[16];
    __shared__ int blist[BLCAP];                        //  5 KB
    __shared__ int   cidx [CCAP];                       // 12 KB
    __shared__ unsigned short cmono[CCAP];              //  6 KB
    __shared__ float q[512];                            //  2 KB
    __shared__ int   sI[SEL];
    __shared__ float sE[SEL];
    __shared__ float selS[64];
    __shared__ int   selI[64];
    __shared__ float wgt[64];
    __shared__ int nact_s, ccount;
    __shared__ int bstar_s;
    __shared__ unsigned int cumabove_s, tau_s;

    int row = blockIdx.x, tid = threadIdx.x, lane = tid & 31, wrp = tid >> 5;
    for (int i = tid; i < 4096; i += 256) hist[i] = 0u;
    if (tid == 0) { nact_s = 0; ccount = 0; bstar_s = 0; cumabove_s = 0u; tau_s = 0u; }
    if (tid < 16) h2[tid] = 0u;
    for (int i = tid; i < 512; i += 256) q[i] = g_query[(size_t)row * 512 + i];
    __syncthreads();

    // ---- pass 1: 12-bit hist of blockmaxes ----
    for (int b = tid; b < NB; b += 256)
        atomicAdd(&hist[g_bmax[row * MAXNB + b] >> 4], 1u);
    __syncthreads();

    // segments + warp-parallel exclusive prefix (from top)
    unsigned int s = 0;
#pragma unroll 4
    for (int k = 0; k < 16; k++) s += hist[4095 - (tid * 16 + k)];
    seg[tid] = s;
    __syncthreads();
    if (tid < 32) {
        unsigned int v[8], tot = 0;
#pragma unroll
        for (int k = 0; k < 8; k++) { v[k] = seg[tid * 8 + k]; tot += v[k]; }
        unsigned int sc = tot;
#pragma unroll
        for (int o = 1; o < 32; o <<= 1) {
            unsigned int t = __shfl_up_sync(0xffffffffu, sc, o);
            if (lane >= o) sc += t;
        }
        unsigned int base = sc - tot;
#pragma unroll
        for (int k = 0; k < 8; k++) { pref[tid * 8 + k] = base; base += v[k]; }
    }
    __syncthreads();
    int mk = *pmk; if (mk < 1) mk = 1; if (mk > NB) mk = NB;
    unsigned int need = (unsigned int)mk;
    // locate bin b* containing the mk-th largest blockmax, plus count strictly above b*
    if (pref[tid] < need && pref[tid] + seg[tid] >= need) {
        unsigned int cum = pref[tid];
        for (int k = 0; k < 16; k++) {
            int bin = 4095 - (tid * 16 + k);
            unsigned int hc = hist[bin];
            if (cum + hc >= need) { bstar_s = bin; cumabove_s = cum; break; }
            cum += hc;
        }
    }
    __syncthreads();
    int bstar = bstar_s;

    // ---- pass 2: refine low 4 bits within b* -> exact 16-bit mono tau ----
    for (int b = tid; b < NB; b += 256) {
        unsigned int bm = g_bmax[row * MAXNB + b];
        if ((int)(bm >> 4) == bstar) atomicAdd(&h2[bm & 15u], 1u);
    }
    __syncthreads();
    if (tid == 0) {
        unsigned int cum = cumabove_s;
        unsigned int tau = (unsigned int)(bstar << 4);   // fallback: bin floor
        for (int k = 15; k >= 0; k--) {
            cum += h2[k];
            if (cum >= need) { tau = (unsigned int)((bstar << 4) | k); break; }
        }
        tau_s = tau;
    }
    __syncthreads();
    unsigned int tau16 = tau_s;

    // ---- active block list: bmax >= tau16 (exact) ----
    for (int b = tid; b < NB; b += 256)
        if (g_bmax[row * MAXNB + b] >= tau16) {
            int p = atomicAdd(&nact_s, 1);
            if (p < BLCAP) blist[p] = b;
        }
    __syncthreads();
    int nact = nact_s; if (nact > BLCAP) nact = BLCAP;

    // ---- collect candidates: warp per block, exact 16-bit threshold ----
    const unsigned int* sr = reinterpret_cast<const unsigned int*>(g_scb + (size_t)row * N);
    for (int i = wrp; i < nact; i += 8) {
        int b = blist[i];
#pragma unroll
        for (int j = 0; j < 4; j++) {
            int u32i = b * 128 + lane + j * 32;
            int idx0 = u32i * 2;
            if (idx0 + 1 < N) {
                unsigned int pp = sr[u32i];
                unsigned short m0 = mono16((unsigned short)(pp & 0xFFFF));
                unsigned short m1 = mono16((unsigned short)(pp >> 16));
                if ((unsigned int)m0 >= tau16) {
                    int p = atomicAdd(&ccount, 1);
                    if (p < CCAP) { cidx[p] = idx0; cmono[p] = m0; }
                }
                if ((unsigned int)m1 >= tau16) {
                    int p = atomicAdd(&ccount, 1);
                    if (p < CCAP) { cidx[p] = idx0 + 1; cmono[p] = m1; }
                }
            } else if (idx0 < N) {
                unsigned short m0 = mono16(g_scb[(size_t)row * N + idx0]);
                if ((unsigned int)m0 >= tau16) {
                    int p = atomicAdd(&ccount, 1);
                    if (p < CCAP) { cidx[p] = idx0; cmono[p] = m0; }
                }
            }
        }
    }
    __syncthreads();
    int c = ccount; if (c > CCAP) c = CCAP;

    // ---- coarse rank: (coarse desc, index asc); keep top-SEL indices ----
    int nsel = c < SEL ? c : SEL;
    for (int i = tid; i < c; i += 256) {
        unsigned short mi = cmono[i];
        int idi = cidx[i];
        int r = 0;
        for (int j = 0; j < c; j++) {
            unsigned short mj = cmono[j];
            r += (mj > mi) || (mj == mi && cidx[j] < idi);
        }
        if (r < SEL) sI[r] = idi;
    }
    __syncthreads();

    // ---- exact fp32 rescore of coarse top-SEL: one warp per candidate ----
    for (int cand = wrp; cand < nsel; cand += 8) {
        const float* kr = keys + (size_t)sI[cand] * 512;
        float sm = 0.f;
#pragma unroll
        for (int k = 0; k < 16; k++) sm += kr[lane + k * 32] * q[lane + k * 32];
#pragma unroll
        for (int o = 16; o; o >>= 1) sm += __shfl_xor_sync(0xffffffffu, sm, o);
        if (lane == 0) sE[cand] = sm * INV_SQRT_D;
    }
    __syncthreads();

    // ---- exact rank among nsel: (score desc, index asc) = jax.lax.top_k order ----
    if (tid < nsel) {
        float si = sE[tid]; int idi = sI[tid];
        int r = 0;
        for (int j = 0; j < nsel; j++) {
            float sj = sE[j];
            r += (sj > si) || (sj == si && sI[j] < idi);
        }
        if (r < 64) { selS[r] = si; selI[r] = idi; }
    }
    __syncthreads();
    int kd = *pkd; if (kd > 64) kd = 64; if (kd < 1) kd = 1;
    if (kd > nsel) kd = nsel;
    if (tid == 0) {
        float mx = selS[0];
        float sum = 0.f;
        for (int r = 0; r < kd; r++) { float e = expf(selS[r] - mx); wgt[r] = e; sum += e; }
        float inv = 1.0f / sum;
        for (int r = 0; r < kd; r++) wgt[r] *= inv;
    }
    __syncthreads();
    for (int d = tid; d < 512; d += 256) {
        float acc = 0.f;
#pragma unroll 4
        for (int r = 0; r < kd; r++)
            acc += wgt[r] * pool_params[(size_t)selI[r] * 512 + d];
        out[row * 512 + d] = acc;
    }
}

// ---------------- launch ----------------
extern "C" void kernel_launch(void* const* d_in, const int* in_sizes, int n_in,
                              void* d_out, int out_size) {
    const float* hidden      = (const float*)d_in[0];
    const float* pool_params = (const float*)d_in[1];
    const float* pool_keys   = (const float*)d_in[2];
    const float* W           = (const float*)d_in[3];
    const float* bias        = (const float*)d_in[4];
    const int*   pkd         = (const int*)d_in[5];
    const int*   pmk         = (const int*)d_in[6];

    int B = out_size / 512;          if (B > MAXB) B = MAXB;
    int T = in_sizes[0] / (B * 512);
    int N = in_sizes[2] / 512;       if (N > MAXN) N = MAXN;
    int NB = (N + 255) / 256;

    k_mean<<<dim3(B, 8), 512>>>(hidden, T);
    k_query<<<B, 256>>>(W, bias, T);
    k_scores<<<NB, 128>>>(pool_keys, N);
    k_post<<<B, 256>>>(pool_params, pool_keys, pkd, pmk, (float*)d_out, N, NB);
}